// round 3
// baseline (speedup 1.0000x reference)
#include <cuda_runtime.h>
#include <math.h>

// Problem constants: B=2, L=2048, D=1024, H=16, HD=64, R=512
#define MROWS 4096

// ---------------- scratch (device globals; allocation-free) ----------------
// reuse plan:
//   g_n1 : ln1 out -> attn ctx -> ln2 out
//   g_n2 : x + attn_out (residual stream 1)
//   g_qkv: qkv projection
//   g_big: relu(h@w1+b1)
__device__ float g_n1 [MROWS * 1024];
__device__ float g_n2 [MROWS * 1024];
__device__ float g_qkv[MROWS * 3072];
__device__ float g_big[MROWS * 4096];

__device__ __forceinline__ float* buf_resolve(int code, const float* p)
{
    switch (code) {
        case 1: return g_n1;
        case 2: return g_n2;
        case 3: return g_qkv;
        case 4: return g_big;
        default: return (float*)p;
    }
}

// ---------------- LayerNorm: one block per row, D=1024, 256 thr ----------------
__global__ __launch_bounds__(256) void ln_kernel(const float* __restrict__ xp, int xc,
                                                 const float* __restrict__ gam,
                                                 const float* __restrict__ bet,
                                                 float* op, int oc)
{
    const float* x = buf_resolve(xc, xp);
    float* out = buf_resolve(oc, op);

    __shared__ float sh[8];
    __shared__ float stat[2];
    const int row = blockIdx.x;
    const int t = threadIdx.x;

    const float4 v = reinterpret_cast<const float4*>(x)[(size_t)row * 256 + t];
    float s = v.x + v.y + v.z + v.w;
    #pragma unroll
    for (int o = 16; o; o >>= 1) s += __shfl_xor_sync(0xffffffffu, s, o);
    if ((t & 31) == 0) sh[t >> 5] = s;
    __syncthreads();
    if (t < 32) {
        float u = (t < 8) ? sh[t] : 0.f;
        #pragma unroll
        for (int o = 4; o; o >>= 1) u += __shfl_xor_sync(0xffffffffu, u, o);
        if (t == 0) stat[0] = u * (1.f / 1024.f);
    }
    __syncthreads();
    const float mu = stat[0];
    const float a = v.x - mu, b = v.y - mu, c = v.z - mu, d = v.w - mu;
    float s2 = a * a + b * b + c * c + d * d;
    #pragma unroll
    for (int o = 16; o; o >>= 1) s2 += __shfl_xor_sync(0xffffffffu, s2, o);
    if ((t & 31) == 0) sh[t >> 5] = s2;
    __syncthreads();
    if (t < 32) {
        float u = (t < 8) ? sh[t] : 0.f;
        #pragma unroll
        for (int o = 4; o; o >>= 1) u += __shfl_xor_sync(0xffffffffu, u, o);
        if (t == 0) stat[1] = rsqrtf(u * (1.f / 1024.f) + 1e-5f);
    }
    __syncthreads();
    const float inv = stat[1];
    const float4 gv = reinterpret_cast<const float4*>(gam)[t];
    const float4 bv = reinterpret_cast<const float4*>(bet)[t];
    float4 o4;
    o4.x = a * inv * gv.x + bv.x;
    o4.y = b * inv * gv.y + bv.y;
    o4.z = c * inv * gv.z + bv.z;
    o4.w = d * inv * gv.w + bv.w;
    reinterpret_cast<float4*>(out)[(size_t)row * 256 + t] = o4;
}

// ---------------- SGEMM: C = A[M,K] @ B[K,N] + bias (+res) (+relu) ----------------
// 128x128 block, BK=8, 256 threads, 8x8 microtile. M,N multiple of 128; K multiple of 8.
template<bool RELU, bool RESID>
__global__ __launch_bounds__(256) void sgemm_kernel(
    int M, int N, int K,
    const float* Ap, int Ac,
    const float* __restrict__ B,
    const float* __restrict__ bias,
    const float* resp, int resc,
    float* Cp, int Cc)
{
    const float* A   = buf_resolve(Ac, Ap);
    const float* res = buf_resolve(resc, resp);
    float*       C   = buf_resolve(Cc, Cp);

    __shared__ float As[8 * 128];
    __shared__ float Bs[8 * 128];
    const int tid  = threadIdx.x;
    const int brow = blockIdx.y, bcol = blockIdx.x;
    const int tr = tid >> 4, tc = tid & 15;

    const int am = tid >> 1, ak = (tid & 1) * 4;
    const int bk = tid >> 5, bn = (tid & 31) * 4;

    const float* Aptr = A + (size_t)(brow * 128 + am) * K + ak;
    const float* Bptr = B + (size_t)bk * N + bcol * 128 + bn;

    float acc[8][8];
    #pragma unroll
    for (int i = 0; i < 8; i++)
        #pragma unroll
        for (int j = 0; j < 8; j++) acc[i][j] = 0.f;

    for (int k0 = 0; k0 < K; k0 += 8) {
        const float4 a = *(const float4*)(Aptr + k0);
        const float4 b = *(const float4*)(Bptr + (size_t)k0 * N);
        As[(ak + 0) * 128 + am] = a.x;
        As[(ak + 1) * 128 + am] = a.y;
        As[(ak + 2) * 128 + am] = a.z;
        As[(ak + 3) * 128 + am] = a.w;
        *(float4*)&Bs[bk * 128 + bn] = b;
        __syncthreads();
        #pragma unroll
        for (int kk = 0; kk < 8; kk++) {
            float ar[8], br[8];
            *(float4*)&ar[0] = *(const float4*)&As[kk * 128 + tr * 8];
            *(float4*)&ar[4] = *(const float4*)&As[kk * 128 + tr * 8 + 4];
            *(float4*)&br[0] = *(const float4*)&Bs[kk * 128 + tc * 8];
            *(float4*)&br[4] = *(const float4*)&Bs[kk * 128 + tc * 8 + 4];
            #pragma unroll
            for (int i = 0; i < 8; i++)
                #pragma unroll
                for (int j = 0; j < 8; j++)
                    acc[i][j] = fmaf(ar[i], br[j], acc[i][j]);
        }
        __syncthreads();
    }

    const int cb = bcol * 128 + tc * 8;
    const float4 bias0 = *(const float4*)(bias + cb);
    const float4 bias1 = *(const float4*)(bias + cb + 4);
    #pragma unroll
    for (int i = 0; i < 8; i++) {
        const size_t off = (size_t)(brow * 128 + tr * 8 + i) * N + cb;
        float4 v0, v1;
        v0.x = acc[i][0] + bias0.x; v0.y = acc[i][1] + bias0.y;
        v0.z = acc[i][2] + bias0.z; v0.w = acc[i][3] + bias0.w;
        v1.x = acc[i][4] + bias1.x; v1.y = acc[i][5] + bias1.y;
        v1.z = acc[i][6] + bias1.z; v1.w = acc[i][7] + bias1.w;
        if (RESID) {
            const float4 r0 = *(const float4*)(res + off);
            const float4 r1 = *(const float4*)(res + off + 4);
            v0.x += r0.x; v0.y += r0.y; v0.z += r0.z; v0.w += r0.w;
            v1.x += r1.x; v1.y += r1.y; v1.z += r1.z; v1.w += r1.w;
        }
        if (RELU) {
            v0.x = fmaxf(v0.x, 0.f); v0.y = fmaxf(v0.y, 0.f);
            v0.z = fmaxf(v0.z, 0.f); v0.w = fmaxf(v0.w, 0.f);
            v1.x = fmaxf(v1.x, 0.f); v1.y = fmaxf(v1.y, 0.f);
            v1.z = fmaxf(v1.z, 0.f); v1.w = fmaxf(v1.w, 0.f);
        }
        *(float4*)(C + off)     = v0;
        *(float4*)(C + off + 4) = v1;
    }
}

// ---------------- Windowed flash attention ----------------
// rel_pos bias finite only for 0 <= q-k < 512 -> per 64-row q tile only <=9 k tiles.
// Block = (q_tile, head, batch); 256 threads; 4x4 microtile of the 64x64 tile.
// Static smem = exactly 48KB: Qs[64*64] + KtS[64*64] (aliased by P) + Vs[64*64].
// KtS layout: KtS[d*64 + (c ^ (d&28))]  -> conflict-free float4 reads per d.
// P   layout: P [r*64 + (c ^ (r&28))]   -> conflict-free broadcast reads per kk.
__global__ __launch_bounds__(256) void attn_kernel(const float* __restrict__ res_pos)
{
    const float* qkv = g_qkv;
    float* ctx = g_n1;

    __shared__ float Qs [64 * 64];
    __shared__ float KtS[64 * 64];   // aliased as P after S is computed
    __shared__ float Vs [64 * 64];
    float* P = KtS;

    const int qt = blockIdx.x;            // 0..31
    const int h  = blockIdx.y;            // 0..15
    const int bb = blockIdx.z;            // 0..1
    const int q0 = qt * 64;
    const int tid = threadIdx.x;
    const int tx = tid & 15, ty = tid >> 4;
    const int row0 = ty * 4;              // microtile rows row0..row0+3
    const int col0 = tx * 4;              // microtile cols col0..col0+3

    // load Q tile row-major (coalesced, conflict-free)
    const float* qbase = qkv + ((size_t)(bb * 2048 + q0)) * 3072 + h * 64;
    #pragma unroll
    for (int it = 0; it < 16; it++) {
        const int idx = it * 256 + tid;
        const int r = idx >> 6, d = idx & 63;
        Qs[r * 64 + d] = qbase[(size_t)r * 3072 + d];
    }

    float m_i[4], l_i[4], oo[4][4];
    #pragma unroll
    for (int i = 0; i < 4; i++) {
        m_i[i] = -1e30f; l_i[i] = 0.f;
        #pragma unroll
        for (int j = 0; j < 4; j++) oo[i][j] = 0.f;
    }

    int lo = q0 - 511; if (lo < 0) lo = 0;
    const int kt_lo = lo >> 6;

    for (int kt = kt_lo; kt <= qt; kt++) {
        __syncthreads();   // (a) prior P/V reads complete before overwrite
        const float* kbase = qkv + ((size_t)(bb * 2048 + kt * 64)) * 3072 + 1024 + h * 64;
        const float* vbase = kbase + 1024;
        #pragma unroll
        for (int it = 0; it < 16; it++) {
            const int idx = it * 256 + tid;
            const int c = idx >> 6, d = idx & 63;
            KtS[d * 64 + (c ^ (d & 28))] = kbase[(size_t)c * 3072 + d];
            Vs[c * 64 + d]               = vbase[(size_t)c * 3072 + d];
        }
        __syncthreads();   // (b) K/V visible

        // S = Q K^T (64x64), outer-product over d
        float s[4][4];
        #pragma unroll
        for (int i = 0; i < 4; i++)
            #pragma unroll
            for (int j = 0; j < 4; j++) s[i][j] = 0.f;

        for (int d0 = 0; d0 < 64; d0 += 4) {
            float qv[4][4];
            #pragma unroll
            for (int i = 0; i < 4; i++)
                *(float4*)qv[i] = *(const float4*)&Qs[(row0 + i) * 64 + d0];
            #pragma unroll
            for (int dd = 0; dd < 4; dd++) {
                const int d = d0 + dd;
                float kv[4];
                *(float4*)kv = *(const float4*)&KtS[d * 64 + (col0 ^ (d & 28))];
                #pragma unroll
                for (int i = 0; i < 4; i++)
                    #pragma unroll
                    for (int j = 0; j < 4; j++)
                        s[i][j] = fmaf(qv[i][dd], kv[j], s[i][j]);
            }
        }

        // scale + rel-pos bias (L1-resident via __ldg) + window mask
        #pragma unroll
        for (int i = 0; i < 4; i++) {
            const int q = q0 + row0 + i;
            #pragma unroll
            for (int j = 0; j < 4; j++) {
                const int k = kt * 64 + col0 + j;
                const int dd = q - k;
                s[i][j] = (dd >= 0 && dd < 512)
                        ? s[i][j] * 0.125f + __ldg(&res_pos[h * 512 + dd])
                        : -1e30f;
            }
        }

        // online softmax (row reduce across the 16 tx lanes of each half-warp)
        #pragma unroll
        for (int i = 0; i < 4; i++) {
            float mt = fmaxf(fmaxf(s[i][0], s[i][1]), fmaxf(s[i][2], s[i][3]));
            #pragma unroll
            for (int o = 8; o; o >>= 1) mt = fmaxf(mt, __shfl_xor_sync(0xffffffffu, mt, o));
            const float mn = fmaxf(m_i[i], mt);
            const float alpha = __expf(m_i[i] - mn);
            m_i[i] = mn;
            float rs = 0.f;
            #pragma unroll
            for (int j = 0; j < 4; j++) { s[i][j] = __expf(s[i][j] - mn); rs += s[i][j]; }
            #pragma unroll
            for (int o = 8; o; o >>= 1) rs += __shfl_xor_sync(0xffffffffu, rs, o);
            l_i[i] = l_i[i] * alpha + rs;
            #pragma unroll
            for (int j = 0; j < 4; j++) oo[i][j] *= alpha;
        }

        __syncthreads();   // (c) all warps done reading KtS before P overwrites it

        // store P (row-major with per-row XOR swizzle) - float4 per row
        #pragma unroll
        for (int i = 0; i < 4; i++) {
            const int r = row0 + i;
            float4 pv;
            pv.x = s[i][0]; pv.y = s[i][1]; pv.z = s[i][2]; pv.w = s[i][3];
            *(float4*)&P[r * 64 + (col0 ^ (r & 28))] = pv;
        }
        __syncthreads();   // (d) P visible

        // O += P @ V
        #pragma unroll 4
        for (int kk = 0; kk < 64; kk++) {
            float ar[4], bc[4];
            #pragma unroll
            for (int i = 0; i < 4; i++) {
                const int r = row0 + i;
                ar[i] = P[r * 64 + (kk ^ (r & 28))];
            }
            *(float4*)bc = *(const float4*)&Vs[kk * 64 + col0];
            #pragma unroll
            for (int i = 0; i < 4; i++)
                #pragma unroll
                for (int j = 0; j < 4; j++)
                    oo[i][j] = fmaf(ar[i], bc[j], oo[i][j]);
        }
    }

    #pragma unroll
    for (int i = 0; i < 4; i++) {
        const int q = q0 + row0 + i;
        const float rl = 1.f / l_i[i];
        float4 ov;
        ov.x = oo[i][0] * rl; ov.y = oo[i][1] * rl;
        ov.z = oo[i][2] * rl; ov.w = oo[i][3] * rl;
        *(float4*)&ctx[((size_t)(bb * 2048 + q)) * 1024 + h * 64 + col0] = ov;
    }
}

// ---------------- launch: kernel launches ONLY (no other runtime APIs) ----------------
extern "C" void kernel_launch(void* const* d_in, const int* in_sizes, int n_in,
                              void* d_out, int out_size)
{
    (void)in_sizes; (void)n_in; (void)out_size;
    const float* x      = (const float*)d_in[0];
    const float* respos = (const float*)d_in[1];
    const float* w_qkv  = (const float*)d_in[2];
    const float* b_qkv  = (const float*)d_in[3];
    const float* w_out  = (const float*)d_in[4];
    const float* b_out  = (const float*)d_in[5];
    const float* w1     = (const float*)d_in[6];
    const float* b1     = (const float*)d_in[7];
    const float* w2     = (const float*)d_in[8];
    const float* b2     = (const float*)d_in[9];
    const float* ln1_g  = (const float*)d_in[10];
    const float* ln1_b  = (const float*)d_in[11];
    const float* ln2_g  = (const float*)d_in[12];
    const float* ln2_b  = (const float*)d_in[13];
    float* out = (float*)d_out;

    // 1. xn = ln1(x)                     -> g_n1 (code 1)
    ln_kernel<<<MROWS, 256>>>(x, 0, ln1_g, ln1_b, nullptr, 1);
    // 2. qkv = xn @ w_qkv + b_qkv        -> g_qkv (code 3)   [4096,3072]
    sgemm_kernel<false, false><<<dim3(3072 / 128, 4096 / 128), 256>>>(
        4096, 3072, 1024, nullptr, 1, w_qkv, b_qkv, nullptr, 0, nullptr, 3);
    // 3. windowed flash attention        -> ctx in g_n1
    attn_kernel<<<dim3(32, 16, 2), 256>>>(respos);
    // 4. x1 = x + ctx @ w_out + b_out    -> g_n2 (code 2)
    sgemm_kernel<false, true><<<dim3(1024 / 128, 4096 / 128), 256>>>(
        4096, 1024, 1024, nullptr, 1, w_out, b_out, x, 0, nullptr, 2);
    // 5. h = ln2(x1)                     -> g_n1
    ln_kernel<<<MROWS, 256>>>(nullptr, 2, ln2_g, ln2_b, nullptr, 1);
    // 6. ffn1 = relu(h @ w1 + b1)        -> g_big (code 4)   [4096,4096]
    sgemm_kernel<true, false><<<dim3(4096 / 128, 4096 / 128), 256>>>(
        4096, 4096, 1024, nullptr, 1, w1, b1, nullptr, 0, nullptr, 4);
    // 7. out = x1 + ffn1 @ w2 + b2       -> d_out
    sgemm_kernel<false, true><<<dim3(1024 / 128, 4096 / 128), 256>>>(
        4096, 1024, 4096, nullptr, 4, w2, b2, nullptr, 2, out, 0);
}

// round 4
// speedup vs baseline: 1.0016x; 1.0016x over previous
#include <cuda_runtime.h>
#include <math.h>

// Problem constants: B=2, L=2048, D=1024, H=16, HD=64, R=512
#define MROWS 4096

// ---------------- scratch (device globals; allocation-free) ----------------
// reuse plan:
//   g_n1 : ln1 out -> attn ctx -> ln2 out
//   g_n2 : x + attn_out (residual stream 1)
//   g_qkv: qkv projection
//   g_big: relu(h@w1+b1)
__device__ float g_n1 [MROWS * 1024];
__device__ float g_n2 [MROWS * 1024];
__device__ float g_qkv[MROWS * 3072];
__device__ float g_big[MROWS * 4096];

__device__ __forceinline__ float* buf_resolve(int code, const float* p)
{
    switch (code) {
        case 1: return g_n1;
        case 2: return g_n2;
        case 3: return g_qkv;
        case 4: return g_big;
        default: return (float*)p;
    }
}

// ---------------- LayerNorm: one block per row, D=1024, 256 thr ----------------
__global__ __launch_bounds__(256) void ln_kernel(const float* __restrict__ xp, int xc,
                                                 const float* __restrict__ gam,
                                                 const float* __restrict__ bet,
                                                 float* op, int oc)
{
    const float* x = buf_resolve(xc, xp);
    float* out = buf_resolve(oc, op);

    __shared__ float sh[8];
    __shared__ float stat[2];
    const int row = blockIdx.x;
    const int t = threadIdx.x;

    const float4 v = reinterpret_cast<const float4*>(x)[(size_t)row * 256 + t];
    float s = v.x + v.y + v.z + v.w;
    #pragma unroll
    for (int o = 16; o; o >>= 1) s += __shfl_xor_sync(0xffffffffu, s, o);
    if ((t & 31) == 0) sh[t >> 5] = s;
    __syncthreads();
    if (t < 32) {
        float u = (t < 8) ? sh[t] : 0.f;
        #pragma unroll
        for (int o = 4; o; o >>= 1) u += __shfl_xor_sync(0xffffffffu, u, o);
        if (t == 0) stat[0] = u * (1.f / 1024.f);
    }
    __syncthreads();
    const float mu = stat[0];
    const float a = v.x - mu, b = v.y - mu, c = v.z - mu, d = v.w - mu;
    float s2 = a * a + b * b + c * c + d * d;
    #pragma unroll
    for (int o = 16; o; o >>= 1) s2 += __shfl_xor_sync(0xffffffffu, s2, o);
    if ((t & 31) == 0) sh[t >> 5] = s2;
    __syncthreads();
    if (t < 32) {
        float u = (t < 8) ? sh[t] : 0.f;
        #pragma unroll
        for (int o = 4; o; o >>= 1) u += __shfl_xor_sync(0xffffffffu, u, o);
        if (t == 0) stat[1] = rsqrtf(u * (1.f / 1024.f) + 1e-5f);
    }
    __syncthreads();
    const float inv = stat[1];
    const float4 gv = reinterpret_cast<const float4*>(gam)[t];
    const float4 bv = reinterpret_cast<const float4*>(bet)[t];
    float4 o4;
    o4.x = a * inv * gv.x + bv.x;
    o4.y = b * inv * gv.y + bv.y;
    o4.z = c * inv * gv.z + bv.z;
    o4.w = d * inv * gv.w + bv.w;
    reinterpret_cast<float4*>(out)[(size_t)row * 256 + t] = o4;
}

// ---------------- SGEMM: C = A[M,K] @ B[K,N] + bias (+res) (+relu) ----------------
// 128x128 block, BK=8, 256 threads, 8x8 microtile. M,N multiple of 128; K multiple of 8.
template<bool RELU, bool RESID>
__global__ __launch_bounds__(256) void sgemm_kernel(
    int M, int N, int K,
    const float* Ap, int Ac,
    const float* __restrict__ B,
    const float* __restrict__ bias,
    const float* resp, int resc,
    float* Cp, int Cc)
{
    const float* A   = buf_resolve(Ac, Ap);
    const float* res = buf_resolve(resc, resp);
    float*       C   = buf_resolve(Cc, Cp);

    __shared__ float As[8 * 128];
    __shared__ float Bs[8 * 128];
    const int tid  = threadIdx.x;
    const int brow = blockIdx.y, bcol = blockIdx.x;
    const int tr = tid >> 4, tc = tid & 15;

    const int am = tid >> 1, ak = (tid & 1) * 4;
    const int bk = tid >> 5, bn = (tid & 31) * 4;

    const float* Aptr = A + (size_t)(brow * 128 + am) * K + ak;
    const float* Bptr = B + (size_t)bk * N + bcol * 128 + bn;

    float acc[8][8];
    #pragma unroll
    for (int i = 0; i < 8; i++)
        #pragma unroll
        for (int j = 0; j < 8; j++) acc[i][j] = 0.f;

    for (int k0 = 0; k0 < K; k0 += 8) {
        const float4 a = *(const float4*)(Aptr + k0);
        const float4 b = *(const float4*)(Bptr + (size_t)k0 * N);
        As[(ak + 0) * 128 + am] = a.x;
        As[(ak + 1) * 128 + am] = a.y;
        As[(ak + 2) * 128 + am] = a.z;
        As[(ak + 3) * 128 + am] = a.w;
        *(float4*)&Bs[bk * 128 + bn] = b;
        __syncthreads();
        #pragma unroll
        for (int kk = 0; kk < 8; kk++) {
            float ar[8], br[8];
            *(float4*)&ar[0] = *(const float4*)&As[kk * 128 + tr * 8];
            *(float4*)&ar[4] = *(const float4*)&As[kk * 128 + tr * 8 + 4];
            *(float4*)&br[0] = *(const float4*)&Bs[kk * 128 + tc * 8];
            *(float4*)&br[4] = *(const float4*)&Bs[kk * 128 + tc * 8 + 4];
            #pragma unroll
            for (int i = 0; i < 8; i++)
                #pragma unroll
                for (int j = 0; j < 8; j++)
                    acc[i][j] = fmaf(ar[i], br[j], acc[i][j]);
        }
        __syncthreads();
    }

    const int cb = bcol * 128 + tc * 8;
    const float4 bias0 = *(const float4*)(bias + cb);
    const float4 bias1 = *(const float4*)(bias + cb + 4);
    #pragma unroll
    for (int i = 0; i < 8; i++) {
        const size_t off = (size_t)(brow * 128 + tr * 8 + i) * N + cb;
        float4 v0, v1;
        v0.x = acc[i][0] + bias0.x; v0.y = acc[i][1] + bias0.y;
        v0.z = acc[i][2] + bias0.z; v0.w = acc[i][3] + bias0.w;
        v1.x = acc[i][4] + bias1.x; v1.y = acc[i][5] + bias1.y;
        v1.z = acc[i][6] + bias1.z; v1.w = acc[i][7] + bias1.w;
        if (RESID) {
            const float4 r0 = *(const float4*)(res + off);
            const float4 r1 = *(const float4*)(res + off + 4);
            v0.x += r0.x; v0.y += r0.y; v0.z += r0.z; v0.w += r0.w;
            v1.x += r1.x; v1.y += r1.y; v1.z += r1.z; v1.w += r1.w;
        }
        if (RELU) {
            v0.x = fmaxf(v0.x, 0.f); v0.y = fmaxf(v0.y, 0.f);
            v0.z = fmaxf(v0.z, 0.f); v0.w = fmaxf(v0.w, 0.f);
            v1.x = fmaxf(v1.x, 0.f); v1.y = fmaxf(v1.y, 0.f);
            v1.z = fmaxf(v1.z, 0.f); v1.w = fmaxf(v1.w, 0.f);
        }
        *(float4*)(C + off)     = v0;
        *(float4*)(C + off + 4) = v1;
    }
}

// ---------------- Windowed flash attention ----------------
// rel_pos bias finite only for 0 <= q-k < 512 -> per 64-row q tile only <=9 k tiles.
// Block = (q_tile, head, batch); 256 threads; 4x4 microtile of the 64x64 tile.
// Static smem = exactly 48KB: Qs[64*64] + KtS[64*64] (aliased by P) + Vs[64*64].
// KtS layout: KtS[d*64 + (c ^ (d&28))]  -> conflict-free float4 reads per d.
// P   layout: P [r*64 + (c ^ (r&28))]   -> conflict-free broadcast reads per kk.
__global__ __launch_bounds__(256) void attn_kernel(const float* __restrict__ res_pos)
{
    const float* qkv = g_qkv;
    float* ctx = g_n1;

    __shared__ float Qs [64 * 64];
    __shared__ float KtS[64 * 64];   // aliased as P after S is computed
    __shared__ float Vs [64 * 64];
    float* P = KtS;

    const int qt = blockIdx.x;            // 0..31
    const int h  = blockIdx.y;            // 0..15
    const int bb = blockIdx.z;            // 0..1
    const int q0 = qt * 64;
    const int tid = threadIdx.x;
    const int tx = tid & 15, ty = tid >> 4;
    const int row0 = ty * 4;              // microtile rows row0..row0+3
    const int col0 = tx * 4;              // microtile cols col0..col0+3

    // load Q tile row-major (coalesced, conflict-free)
    const float* qbase = qkv + ((size_t)(bb * 2048 + q0)) * 3072 + h * 64;
    #pragma unroll
    for (int it = 0; it < 16; it++) {
        const int idx = it * 256 + tid;
        const int r = idx >> 6, d = idx & 63;
        Qs[r * 64 + d] = qbase[(size_t)r * 3072 + d];
    }

    float m_i[4], l_i[4], oo[4][4];
    #pragma unroll
    for (int i = 0; i < 4; i++) {
        m_i[i] = -1e30f; l_i[i] = 0.f;
        #pragma unroll
        for (int j = 0; j < 4; j++) oo[i][j] = 0.f;
    }

    int lo = q0 - 511; if (lo < 0) lo = 0;
    const int kt_lo = lo >> 6;

    for (int kt = kt_lo; kt <= qt; kt++) {
        __syncthreads();   // (a) prior P/V reads complete before overwrite
        const float* kbase = qkv + ((size_t)(bb * 2048 + kt * 64)) * 3072 + 1024 + h * 64;
        const float* vbase = kbase + 1024;
        #pragma unroll
        for (int it = 0; it < 16; it++) {
            const int idx = it * 256 + tid;
            const int c = idx >> 6, d = idx & 63;
            KtS[d * 64 + (c ^ (d & 28))] = kbase[(size_t)c * 3072 + d];
            Vs[c * 64 + d]               = vbase[(size_t)c * 3072 + d];
        }
        __syncthreads();   // (b) K/V visible

        // S = Q K^T (64x64), outer-product over d
        float s[4][4];
        #pragma unroll
        for (int i = 0; i < 4; i++)
            #pragma unroll
            for (int j = 0; j < 4; j++) s[i][j] = 0.f;

        for (int d0 = 0; d0 < 64; d0 += 4) {
            float qv[4][4];
            #pragma unroll
            for (int i = 0; i < 4; i++)
                *(float4*)qv[i] = *(const float4*)&Qs[(row0 + i) * 64 + d0];
            #pragma unroll
            for (int dd = 0; dd < 4; dd++) {
                const int d = d0 + dd;
                float kv[4];
                *(float4*)kv = *(const float4*)&KtS[d * 64 + (col0 ^ (d & 28))];
                #pragma unroll
                for (int i = 0; i < 4; i++)
                    #pragma unroll
                    for (int j = 0; j < 4; j++)
                        s[i][j] = fmaf(qv[i][dd], kv[j], s[i][j]);
            }
        }

        // scale + rel-pos bias (L1-resident via __ldg) + window mask
        #pragma unroll
        for (int i = 0; i < 4; i++) {
            const int q = q0 + row0 + i;
            #pragma unroll
            for (int j = 0; j < 4; j++) {
                const int k = kt * 64 + col0 + j;
                const int dd = q - k;
                s[i][j] = (dd >= 0 && dd < 512)
                        ? s[i][j] * 0.125f + __ldg(&res_pos[h * 512 + dd])
                        : -1e30f;
            }
        }

        // online softmax (row reduce across the 16 tx lanes of each half-warp)
        #pragma unroll
        for (int i = 0; i < 4; i++) {
            float mt = fmaxf(fmaxf(s[i][0], s[i][1]), fmaxf(s[i][2], s[i][3]));
            #pragma unroll
            for (int o = 8; o; o >>= 1) mt = fmaxf(mt, __shfl_xor_sync(0xffffffffu, mt, o));
            const float mn = fmaxf(m_i[i], mt);
            const float alpha = __expf(m_i[i] - mn);
            m_i[i] = mn;
            float rs = 0.f;
            #pragma unroll
            for (int j = 0; j < 4; j++) { s[i][j] = __expf(s[i][j] - mn); rs += s[i][j]; }
            #pragma unroll
            for (int o = 8; o; o >>= 1) rs += __shfl_xor_sync(0xffffffffu, rs, o);
            l_i[i] = l_i[i] * alpha + rs;
            #pragma unroll
            for (int j = 0; j < 4; j++) oo[i][j] *= alpha;
        }

        __syncthreads();   // (c) all warps done reading KtS before P overwrites it

        // store P (row-major with per-row XOR swizzle) - float4 per row
        #pragma unroll
        for (int i = 0; i < 4; i++) {
            const int r = row0 + i;
            float4 pv;
            pv.x = s[i][0]; pv.y = s[i][1]; pv.z = s[i][2]; pv.w = s[i][3];
            *(float4*)&P[r * 64 + (col0 ^ (r & 28))] = pv;
        }
        __syncthreads();   // (d) P visible

        // O += P @ V
        #pragma unroll 4
        for (int kk = 0; kk < 64; kk++) {
            float ar[4], bc[4];
            #pragma unroll
            for (int i = 0; i < 4; i++) {
                const int r = row0 + i;
                ar[i] = P[r * 64 + (kk ^ (r & 28))];
            }
            *(float4*)bc = *(const float4*)&Vs[kk * 64 + col0];
            #pragma unroll
            for (int i = 0; i < 4; i++)
                #pragma unroll
                for (int j = 0; j < 4; j++)
                    oo[i][j] = fmaf(ar[i], bc[j], oo[i][j]);
        }
    }

    #pragma unroll
    for (int i = 0; i < 4; i++) {
        const int q = q0 + row0 + i;
        const float rl = 1.f / l_i[i];
        float4 ov;
        ov.x = oo[i][0] * rl; ov.y = oo[i][1] * rl;
        ov.z = oo[i][2] * rl; ov.w = oo[i][3] * rl;
        *(float4*)&ctx[((size_t)(bb * 2048 + q)) * 1024 + h * 64 + col0] = ov;
    }
}

// ---------------- launch: kernel launches ONLY (no other runtime APIs) ----------------
extern "C" void kernel_launch(void* const* d_in, const int* in_sizes, int n_in,
                              void* d_out, int out_size)
{
    (void)in_sizes; (void)n_in; (void)out_size;
    const float* x      = (const float*)d_in[0];
    const float* respos = (const float*)d_in[1];
    const float* w_qkv  = (const float*)d_in[2];
    const float* b_qkv  = (const float*)d_in[3];
    const float* w_out  = (const float*)d_in[4];
    const float* b_out  = (const float*)d_in[5];
    const float* w1     = (const float*)d_in[6];
    const float* b1     = (const float*)d_in[7];
    const float* w2     = (const float*)d_in[8];
    const float* b2     = (const float*)d_in[9];
    const float* ln1_g  = (const float*)d_in[10];
    const float* ln1_b  = (const float*)d_in[11];
    const float* ln2_g  = (const float*)d_in[12];
    const float* ln2_b  = (const float*)d_in[13];
    float* out = (float*)d_out;

    // 1. xn = ln1(x)                     -> g_n1 (code 1)
    ln_kernel<<<MROWS, 256>>>(x, 0, ln1_g, ln1_b, nullptr, 1);
    // 2. qkv = xn @ w_qkv + b_qkv        -> g_qkv (code 3)   [4096,3072]
    sgemm_kernel<false, false><<<dim3(3072 / 128, 4096 / 128), 256>>>(
        4096, 3072, 1024, nullptr, 1, w_qkv, b_qkv, nullptr, 0, nullptr, 3);
    // 3. windowed flash attention        -> ctx in g_n1
    attn_kernel<<<dim3(32, 16, 2), 256>>>(respos);
    // 4. x1 = x + ctx @ w_out + b_out    -> g_n2 (code 2)
    sgemm_kernel<false, true><<<dim3(1024 / 128, 4096 / 128), 256>>>(
        4096, 1024, 1024, nullptr, 1, w_out, b_out, x, 0, nullptr, 2);
    // 5. h = ln2(x1)                     -> g_n1
    ln_kernel<<<MROWS, 256>>>(nullptr, 2, ln2_g, ln2_b, nullptr, 1);
    // 6. ffn1 = relu(h @ w1 + b1)        -> g_big (code 4)   [4096,4096]
    sgemm_kernel<true, false><<<dim3(4096 / 128, 4096 / 128), 256>>>(
        4096, 4096, 1024, nullptr, 1, w1, b1, nullptr, 0, nullptr, 4);
    // 7. out = x1 + ffn1 @ w2 + b2       -> d_out
    sgemm_kernel<false, true><<<dim3(1024 / 128, 4096 / 128), 256>>>(
        4096, 1024, 4096, nullptr, 4, w2, b2, nullptr, 2, out, 0);
}

// round 6
// speedup vs baseline: 2.0388x; 2.0357x over previous
#include <cuda_runtime.h>
#include <cuda_bf16.h>
#include <stdint.h>
#include <math.h>

#define MROWS 4096

// ---------------- scratch ----------------
__device__ __nv_bfloat16 g_ln_aug  [(size_t)MROWS * 3072];
__device__ __nv_bfloat16 g_ctx_aug [(size_t)MROWS * 3072];
__device__ __nv_bfloat16 g_wqkv_aug[(size_t)3072 * 3072];
__device__ __nv_bfloat16 g_wout_aug[(size_t)3072 * 1024];
__device__ __nv_bfloat16 g_w1_aug  [(size_t)3072 * 4096];
__device__ __nv_bfloat16 g_w2_aug  [(size_t)12288 * 1024];
__device__ __nv_bfloat16 g_ffn1_aug[(size_t)MROWS * 12288];
__device__ float g_qkv[(size_t)MROWS * 3072];
__device__ float g_x1 [(size_t)MROWS * 1024];

__device__ __forceinline__ const __nv_bfloat16* bufb(int c)
{
    switch (c) {
        case 1: return g_ln_aug;
        case 2: return g_ctx_aug;
        case 3: return g_wqkv_aug;
        case 4: return g_wout_aug;
        case 5: return g_w1_aug;
        case 6: return g_w2_aug;
        default: return g_ffn1_aug;
    }
}
__device__ __forceinline__ float* buff(int c, const float* p)
{
    switch (c) {
        case 1: return g_qkv;
        case 2: return g_x1;
        default: return (float*)p;
    }
}
__device__ __forceinline__ void bsplit(float v, __nv_bfloat16& hi, __nv_bfloat16& lo)
{
    hi = __float2bfloat16_rn(v);
    lo = __float2bfloat16_rn(v - __bfloat162float(hi));
}

// ---------------- PTX helpers (baseline PTX only; no arch-suffix features) ---
__device__ __forceinline__ uint32_t smem_u32(const void* p)
{
    uint32_t a;
    asm("{ .reg .u64 t; cvta.to.shared.u64 t, %1; cvt.u32.u64 %0, t; }" : "=r"(a) : "l"(p));
    return a;
}
__device__ __forceinline__ void ldm_x4(uint32_t* r, uint32_t a)
{
    asm volatile("ldmatrix.sync.aligned.m8n8.x4.shared.b16 {%0,%1,%2,%3}, [%4];"
        : "=r"(r[0]), "=r"(r[1]), "=r"(r[2]), "=r"(r[3]) : "r"(a));
}
__device__ __forceinline__ void ldm_x4_t(uint32_t* r, uint32_t a)
{
    asm volatile("ldmatrix.sync.aligned.m8n8.x4.trans.shared.b16 {%0,%1,%2,%3}, [%4];"
        : "=r"(r[0]), "=r"(r[1]), "=r"(r[2]), "=r"(r[3]) : "r"(a));
}
__device__ __forceinline__ void mma_bf16(float* c, const uint32_t* a, const uint32_t* b)
{
    asm volatile("mma.sync.aligned.m16n8k16.row.col.f32.bf16.bf16.f32 "
        "{%0,%1,%2,%3}, {%4,%5,%6,%7}, {%8,%9}, {%0,%1,%2,%3};"
        : "+f"(c[0]), "+f"(c[1]), "+f"(c[2]), "+f"(c[3])
        : "r"(a[0]), "r"(a[1]), "r"(a[2]), "r"(a[3]), "r"(b[0]), "r"(b[1]));
}

// ---------------- weight split: w[K,N] f32 -> [hi;lo;hi] bf16 ----------------
__global__ __launch_bounds__(256) void split_w_kernel(const float* __restrict__ w,
                                                      int oc, size_t KN)
{
    __nv_bfloat16* out = (__nv_bfloat16*)bufb(oc);
    const size_t i = (size_t)blockIdx.x * 256 + threadIdx.x;
    const float4 v = reinterpret_cast<const float4*>(w)[i];
    __nv_bfloat16 h0, l0, h1, l1, h2, l2, h3, l3;
    bsplit(v.x, h0, l0); bsplit(v.y, h1, l1); bsplit(v.z, h2, l2); bsplit(v.w, h3, l3);
    const size_t e = i * 4;
    __nv_bfloat162 hA, hB, lA, lB;
    hA.x = h0; hA.y = h1; hB.x = h2; hB.y = h3;
    lA.x = l0; lA.y = l1; lB.x = l2; lB.y = l3;
    *(__nv_bfloat162*)&out[e]          = hA; *(__nv_bfloat162*)&out[e + 2]          = hB;
    *(__nv_bfloat162*)&out[KN + e]     = lA; *(__nv_bfloat162*)&out[KN + e + 2]     = lB;
    *(__nv_bfloat162*)&out[2 * KN + e] = hA; *(__nv_bfloat162*)&out[2 * KN + e + 2] = hB;
}

// ---------------- LayerNorm -> augmented bf16 [row, hi|hi|lo] ----------------
__global__ __launch_bounds__(256) void ln_aug_kernel(const float* __restrict__ xp, int xc,
                                                     const float* __restrict__ gam,
                                                     const float* __restrict__ bet)
{
    const float* x = buff(xc, xp);
    __shared__ float sh[8];
    __shared__ float stat[2];
    const int row = blockIdx.x, t = threadIdx.x;

    const float4 v = reinterpret_cast<const float4*>(x)[(size_t)row * 256 + t];
    float s = v.x + v.y + v.z + v.w;
    #pragma unroll
    for (int o = 16; o; o >>= 1) s += __shfl_xor_sync(0xffffffffu, s, o);
    if ((t & 31) == 0) sh[t >> 5] = s;
    __syncthreads();
    if (t < 32) {
        float u = (t < 8) ? sh[t] : 0.f;
        #pragma unroll
        for (int o = 4; o; o >>= 1) u += __shfl_xor_sync(0xffffffffu, u, o);
        if (t == 0) stat[0] = u * (1.f / 1024.f);
    }
    __syncthreads();
    const float mu = stat[0];
    const float a = v.x - mu, b = v.y - mu, c = v.z - mu, d = v.w - mu;
    float s2 = a * a + b * b + c * c + d * d;
    #pragma unroll
    for (int o = 16; o; o >>= 1) s2 += __shfl_xor_sync(0xffffffffu, s2, o);
    if ((t & 31) == 0) sh[t >> 5] = s2;
    __syncthreads();
    if (t < 32) {
        float u = (t < 8) ? sh[t] : 0.f;
        #pragma unroll
        for (int o = 4; o; o >>= 1) u += __shfl_xor_sync(0xffffffffu, u, o);
        if (t == 0) stat[1] = rsqrtf(u * (1.f / 1024.f) + 1e-5f);
    }
    __syncthreads();
    const float inv = stat[1];
    const float4 gv = reinterpret_cast<const float4*>(gam)[t];
    const float4 bv = reinterpret_cast<const float4*>(bet)[t];
    const float o0 = a * inv * gv.x + bv.x, o1 = b * inv * gv.y + bv.y;
    const float o2 = c * inv * gv.z + bv.z, o3 = d * inv * gv.w + bv.w;
    __nv_bfloat16 h0, l0, h1, l1, h2, l2, h3, l3;
    bsplit(o0, h0, l0); bsplit(o1, h1, l1); bsplit(o2, h2, l2); bsplit(o3, h3, l3);
    __nv_bfloat162 hA, hB, lA, lB;
    hA.x = h0; hA.y = h1; hB.x = h2; hB.y = h3;
    lA.x = l0; lA.y = l1; lB.x = l2; lB.y = l3;
    const size_t base = (size_t)row * 3072 + t * 4;
    *(__nv_bfloat162*)&g_ln_aug[base]        = hA; *(__nv_bfloat162*)&g_ln_aug[base + 2]    = hB;
    *(__nv_bfloat162*)&g_ln_aug[base + 1024] = hA; *(__nv_bfloat162*)&g_ln_aug[base + 1026] = hB;
    *(__nv_bfloat162*)&g_ln_aug[base + 2048] = lA; *(__nv_bfloat162*)&g_ln_aug[base + 2050] = lB;
}

// ---------------- HMMA GEMM: C[128x128/CTA] = A'[M,KT] @ B'[KT,N] ------------
// 256 thr, 8 warps (4m x 2n), warp tile 32x64 = 2x8 m16n8k16 tiles, BK=32,
// double-buffered smem with padded strides (conflict-free ldmatrix phases).
#define AS_STRIDE 40    // 128 rows x 40 bf16 (32 data + 8 pad)
#define BS_STRIDE 136   // 32 rows x 136 bf16 (128 data + 8 pad)

template<bool RELU, bool RESID, bool AUGOUT>
__global__ __launch_bounds__(256) void gemm_mma(
    int N, int KTOT, int Ac, int Bc,
    const float* __restrict__ bias,
    const float* resp, int resc,
    float* Cp, int Cc)
{
    const __nv_bfloat16* A  = bufb(Ac);
    const __nv_bfloat16* Bw = bufb(Bc);
    const float* res = buff(resc, resp);
    float* C = buff(Cc, Cp);

    __shared__ __nv_bfloat16 As[2][128 * AS_STRIDE];
    __shared__ __nv_bfloat16 Bs[2][32 * BS_STRIDE];

    const int tid = threadIdx.x;
    const int wid = tid >> 5, lane = tid & 31;
    const int wm = wid & 3, wn = wid >> 2;      // 4 x 2 warp grid
    const int brow = blockIdx.y, bcol = blockIdx.x;

    const __nv_bfloat16* Ablk = A + (size_t)(brow * 128) * KTOT;
    const __nv_bfloat16* Bblk = Bw + bcol * 128;

    // per-thread gmem->smem coords
    const int arow0 = tid >> 2,            ac8 = tid & 3;        // +64 rows on i=1
    const int brow0 = tid >> 4,            bc8 = tid & 15;       // +16 rows on i=1

    // per-lane ldmatrix base addresses (bytes)
    const int lr = lane & 15, lc = lane >> 4;
    const uint32_t asB = smem_u32(As);
    const uint32_t bsB = smem_u32(Bs);
    const uint32_t aAddr0 = asB + (uint32_t)(((wm * 32 + lr) * AS_STRIDE + lc * 8) * 2);
    const uint32_t bAddr0 = bsB + (uint32_t)((lr * BS_STRIDE + wn * 64 + lc * 8) * 2);

    float acc[2][8][4];
    #pragma unroll
    for (int mt = 0; mt < 2; mt++)
        #pragma unroll
        for (int nt = 0; nt < 8; nt++)
            #pragma unroll
            for (int q = 0; q < 4; q++) acc[mt][nt][q] = 0.f;

    const int NS = KTOT >> 5;

    // preload stage 0
    {
        #pragma unroll
        for (int i = 0; i < 2; i++) {
            const int ra = arow0 + i * 64;
            *(uint4*)&As[0][ra * AS_STRIDE + ac8 * 8] =
                *(const uint4*)(Ablk + (size_t)ra * KTOT + ac8 * 8);
            const int rb = brow0 + i * 16;
            *(uint4*)&Bs[0][rb * BS_STRIDE + bc8 * 8] =
                *(const uint4*)(Bblk + (size_t)rb * N + bc8 * 8);
        }
    }
    __syncthreads();

    #pragma unroll 1
    for (int s = 0; s < NS; s++) {
        const int b = s & 1;
        uint4 pa[2], pb[2];
        const bool pf = (s + 1 < NS);
        if (pf) {
            const int kg = (s + 1) * 32;
            #pragma unroll
            for (int i = 0; i < 2; i++) {
                pa[i] = *(const uint4*)(Ablk + (size_t)(arow0 + i * 64) * KTOT + kg + ac8 * 8);
                pb[i] = *(const uint4*)(Bblk + (size_t)(kg + brow0 + i * 16) * N + bc8 * 8);
            }
        }

        const uint32_t aBuf = aAddr0 + (uint32_t)(b * 128 * AS_STRIDE * 2);
        const uint32_t bBuf = bAddr0 + (uint32_t)(b * 32 * BS_STRIDE * 2);
        #pragma unroll
        for (int ks = 0; ks < 2; ks++) {
            uint32_t af[2][4], bf[4][4];
            ldm_x4(af[0], aBuf + (uint32_t)(ks * 32));
            ldm_x4(af[1], aBuf + (uint32_t)(ks * 32 + 16 * AS_STRIDE * 2));
            #pragma unroll
            for (int n16 = 0; n16 < 4; n16++)
                ldm_x4_t(bf[n16], bBuf + (uint32_t)(ks * 16 * BS_STRIDE * 2 + n16 * 32));
            #pragma unroll
            for (int mt = 0; mt < 2; mt++)
                #pragma unroll
                for (int nt = 0; nt < 8; nt++)
                    mma_bf16(acc[mt][nt], af[mt], &bf[nt >> 1][(nt & 1) * 2]);
        }

        if (pf) {
            const int bn = b ^ 1;
            #pragma unroll
            for (int i = 0; i < 2; i++) {
                *(uint4*)&As[bn][(arow0 + i * 64) * AS_STRIDE + ac8 * 8] = pa[i];
                *(uint4*)&Bs[bn][(brow0 + i * 16) * BS_STRIDE + bc8 * 8] = pb[i];
            }
            __syncthreads();
        }
    }

    // epilogue
    const int rbase = brow * 128 + wm * 32 + (lane >> 2);
    const int cbase = bcol * 128 + wn * 64 + (lane & 3) * 2;
    #pragma unroll
    for (int mt = 0; mt < 2; mt++) {
        #pragma unroll
        for (int nt = 0; nt < 8; nt++) {
            const int c = cbase + nt * 8;
            const float2 bv = *(const float2*)(bias + c);
            #pragma unroll
            for (int hrow = 0; hrow < 2; hrow++) {
                const int r = rbase + mt * 16 + hrow * 8;
                float v0 = acc[mt][nt][hrow * 2]     + bv.x;
                float v1 = acc[mt][nt][hrow * 2 + 1] + bv.y;
                if (AUGOUT) {
                    v0 = fmaxf(v0, 0.f); v1 = fmaxf(v1, 0.f);
                    __nv_bfloat16 h0, l0, h1, l1;
                    bsplit(v0, h0, l0); bsplit(v1, h1, l1);
                    __nv_bfloat162 hp, lp;
                    hp.x = h0; hp.y = h1; lp.x = l0; lp.y = l1;
                    const size_t rb = (size_t)r * 12288 + c;
                    *(__nv_bfloat162*)&g_ffn1_aug[rb]        = hp;
                    *(__nv_bfloat162*)&g_ffn1_aug[rb + 4096] = hp;
                    *(__nv_bfloat162*)&g_ffn1_aug[rb + 8192] = lp;
                } else {
                    const size_t off = (size_t)r * N + c;
                    if (RESID) {
                        const float2 rv = *(const float2*)(res + off);
                        v0 += rv.x; v1 += rv.y;
                    }
                    if (RELU) { v0 = fmaxf(v0, 0.f); v1 = fmaxf(v1, 0.f); }
                    float2 ov; ov.x = v0; ov.y = v1;
                    *(float2*)(C + off) = ov;
                }
            }
        }
    }
}

// ---------------- windowed flash attention (fp32) -> g_ctx_aug ----------------
__global__ __launch_bounds__(256) void attn_kernel(const float* __restrict__ res_pos)
{
    const float* qkv = g_qkv;
    __shared__ float Qs [64 * 64];
    __shared__ float KtS[64 * 64];
    __shared__ float Vs [64 * 64];
    float* P = KtS;

    const int qt = blockIdx.x, h = blockIdx.y, bb = blockIdx.z;
    const int q0 = qt * 64, tid = threadIdx.x;
    const int tx = tid & 15, ty = tid >> 4;
    const int row0 = ty * 4, col0 = tx * 4;

    const float* qbase = qkv + ((size_t)(bb * 2048 + q0)) * 3072 + h * 64;
    #pragma unroll
    for (int it = 0; it < 16; it++) {
        const int idx = it * 256 + tid;
        const int r = idx >> 6, d = idx & 63;
        Qs[r * 64 + d] = qbase[(size_t)r * 3072 + d];
    }

    float m_i[4], l_i[4], oo[4][4];
    #pragma unroll
    for (int i = 0; i < 4; i++) {
        m_i[i] = -1e30f; l_i[i] = 0.f;
        #pragma unroll
        for (int j = 0; j < 4; j++) oo[i][j] = 0.f;
    }

    int lo = q0 - 511; if (lo < 0) lo = 0;
    for (int kt = lo >> 6; kt <= qt; kt++) {
        __syncthreads();
        const float* kbase = qkv + ((size_t)(bb * 2048 + kt * 64)) * 3072 + 1024 + h * 64;
        const float* vbase = kbase + 1024;
        #pragma unroll
        for (int it = 0; it < 16; it++) {
            const int idx = it * 256 + tid;
            const int c = idx >> 6, d = idx & 63;
            KtS[d * 64 + (c ^ (d & 28))] = kbase[(size_t)c * 3072 + d];
            Vs[c * 64 + d]               = vbase[(size_t)c * 3072 + d];
        }
        __syncthreads();

        float s[4][4];
        #pragma unroll
        for (int i = 0; i < 4; i++)
            #pragma unroll
            for (int j = 0; j < 4; j++) s[i][j] = 0.f;
        for (int d0 = 0; d0 < 64; d0 += 4) {
            float qv[4][4];
            #pragma unroll
            for (int i = 0; i < 4; i++)
                *(float4*)qv[i] = *(const float4*)&Qs[(row0 + i) * 64 + d0];
            #pragma unroll
            for (int dd = 0; dd < 4; dd++) {
                const int d = d0 + dd;
                float kv[4];
                *(float4*)kv = *(const float4*)&KtS[d * 64 + (col0 ^ (d & 28))];
                #pragma unroll
                for (int i = 0; i < 4; i++)
                    #pragma unroll
                    for (int j = 0; j < 4; j++)
                        s[i][j] = fmaf(qv[i][dd], kv[j], s[i][j]);
            }
        }
        #pragma unroll
        for (int i = 0; i < 4; i++) {
            const int q = q0 + row0 + i;
            #pragma unroll
            for (int j = 0; j < 4; j++) {
                const int dd = q - (kt * 64 + col0 + j);
                s[i][j] = (dd >= 0 && dd < 512)
                        ? s[i][j] * 0.125f + __ldg(&res_pos[h * 512 + dd]) : -1e30f;
            }
        }
        #pragma unroll
        for (int i = 0; i < 4; i++) {
            float mt = fmaxf(fmaxf(s[i][0], s[i][1]), fmaxf(s[i][2], s[i][3]));
            #pragma unroll
            for (int o = 8; o; o >>= 1) mt = fmaxf(mt, __shfl_xor_sync(0xffffffffu, mt, o));
            const float mn = fmaxf(m_i[i], mt);
            const float alpha = __expf(m_i[i] - mn);
            m_i[i] = mn;
            float rs = 0.f;
            #pragma unroll
            for (int j = 0; j < 4; j++) { s[i][j] = __expf(s[i][j] - mn); rs += s[i][j]; }
            #pragma unroll
            for (int o = 8; o; o >>= 1) rs += __shfl_xor_sync(0xffffffffu, rs, o);
            l_i[i] = l_i[i] * alpha + rs;
            #pragma unroll
            for (int j = 0; j < 4; j++) oo[i][j] *= alpha;
        }
        __syncthreads();
        #pragma unroll
        for (int i = 0; i < 4; i++) {
            const int r = row0 + i;
            float4 pv;
            pv.x = s[i][0]; pv.y = s[i][1]; pv.z = s[i][2]; pv.w = s[i][3];
            *(float4*)&P[r * 64 + (col0 ^ (r & 28))] = pv;
        }
        __syncthreads();
        #pragma unroll 4
        for (int kk = 0; kk < 64; kk++) {
            float ar[4], bc[4];
            #pragma unroll
            for (int i = 0; i < 4; i++) ar[i] = P[(row0 + i) * 64 + (kk ^ ((row0 + i) & 28))];
            *(float4*)bc = *(const float4*)&Vs[kk * 64 + col0];
            #pragma unroll
            for (int i = 0; i < 4; i++)
                #pragma unroll
                for (int j = 0; j < 4; j++)
                    oo[i][j] = fmaf(ar[i], bc[j], oo[i][j]);
        }
    }

    #pragma unroll
    for (int i = 0; i < 4; i++) {
        const float rl = 1.f / l_i[i];
        const size_t base = ((size_t)(bb * 2048 + q0 + row0 + i)) * 3072 + h * 64 + col0;
        __nv_bfloat16 h0, l0h, h1, l1h, h2, l2h, h3, l3h;
        bsplit(oo[i][0] * rl, h0, l0h); bsplit(oo[i][1] * rl, h1, l1h);
        bsplit(oo[i][2] * rl, h2, l2h); bsplit(oo[i][3] * rl, h3, l3h);
        __nv_bfloat162 hA, hB, lA, lB;
        hA.x = h0; hA.y = h1; hB.x = h2; hB.y = h3;
        lA.x = l0h; lA.y = l1h; lB.x = l2h; lB.y = l3h;
        *(__nv_bfloat162*)&g_ctx_aug[base]        = hA; *(__nv_bfloat162*)&g_ctx_aug[base + 2]    = hB;
        *(__nv_bfloat162*)&g_ctx_aug[base + 1024] = hA; *(__nv_bfloat162*)&g_ctx_aug[base + 1026] = hB;
        *(__nv_bfloat162*)&g_ctx_aug[base + 2048] = lA; *(__nv_bfloat162*)&g_ctx_aug[base + 2050] = lB;
    }
}

// ---------------- launch: kernel launches ONLY ----------------
extern "C" void kernel_launch(void* const* d_in, const int* in_sizes, int n_in,
                              void* d_out, int out_size)
{
    (void)in_sizes; (void)n_in; (void)out_size;
    const float* x      = (const float*)d_in[0];
    const float* respos = (const float*)d_in[1];
    const float* w_qkv  = (const float*)d_in[2];
    const float* b_qkv  = (const float*)d_in[3];
    const float* w_out  = (const float*)d_in[4];
    const float* b_out  = (const float*)d_in[5];
    const float* w1     = (const float*)d_in[6];
    const float* b1     = (const float*)d_in[7];
    const float* w2     = (const float*)d_in[8];
    const float* b2     = (const float*)d_in[9];
    const float* ln1_g  = (const float*)d_in[10];
    const float* ln1_b  = (const float*)d_in[11];
    const float* ln2_g  = (const float*)d_in[12];
    const float* ln2_b  = (const float*)d_in[13];
    float* out = (float*)d_out;

    // weight splits: B' = [hi;lo;hi]
    split_w_kernel<<<3072, 256>>>(w_qkv, 3, (size_t)1024 * 3072);
    split_w_kernel<<<1024, 256>>>(w_out, 4, (size_t)1024 * 1024);
    split_w_kernel<<<4096, 256>>>(w1,    5, (size_t)1024 * 4096);
    split_w_kernel<<<4096, 256>>>(w2,    6, (size_t)4096 * 1024);

    // 1. ln1 -> g_ln_aug
    ln_aug_kernel<<<MROWS, 256>>>(x, 0, ln1_g, ln1_b);
    // 2. qkv = ln1' @ wqkv' + b_qkv -> g_qkv (fp32)
    gemm_mma<false, false, false><<<dim3(24, 32), 256>>>(
        3072, 3072, 1, 3, b_qkv, nullptr, 0, nullptr, 1);
    // 3. attention -> g_ctx_aug
    attn_kernel<<<dim3(32, 16, 2), 256>>>(respos);
    // 4. x1 = x + ctx' @ wout' + b_out -> g_x1
    gemm_mma<false, true, false><<<dim3(8, 32), 256>>>(
        1024, 3072, 2, 4, b_out, x, 0, nullptr, 2);
    // 5. ln2 -> g_ln_aug
    ln_aug_kernel<<<MROWS, 256>>>(nullptr, 2, ln2_g, ln2_b);
    // 6. ffn1 = relu(ln2' @ w1' + b1) -> g_ffn1_aug (split epilogue)
    gemm_mma<true, false, true><<<dim3(32, 32), 256>>>(
        4096, 3072, 1, 5, b1, nullptr, 0, nullptr, 0);
    // 7. out = x1 + ffn1' @ w2' + b2 -> d_out
    gemm_mma<false, true, false><<<dim3(8, 32), 256>>>(
        1024, 12288, 7, 6, b2, nullptr, 2, out, 0);
}

// round 7
// speedup vs baseline: 2.0968x; 1.0284x over previous
#include <cuda_runtime.h>
#include <cuda_bf16.h>
#include <stdint.h>
#include <math.h>

#define MROWS 4096

// ---------------- scratch ----------------
__device__ __nv_bfloat16 g_ln_aug  [(size_t)MROWS * 3072];
__device__ __nv_bfloat16 g_ctx_aug [(size_t)MROWS * 3072];
__device__ __nv_bfloat16 g_wqkv_aug[(size_t)3072 * 3072];
__device__ __nv_bfloat16 g_wout_aug[(size_t)3072 * 1024];
__device__ __nv_bfloat16 g_w1_aug  [(size_t)3072 * 4096];
__device__ __nv_bfloat16 g_w2_aug  [(size_t)12288 * 1024];
__device__ __nv_bfloat16 g_ffn1_aug[(size_t)MROWS * 12288];
__device__ float g_qkv[(size_t)MROWS * 3072];
__device__ float g_x1 [(size_t)MROWS * 1024];

__device__ __forceinline__ const __nv_bfloat16* bufb(int c)
{
    switch (c) {
        case 1: return g_ln_aug;
        case 2: return g_ctx_aug;
        case 3: return g_wqkv_aug;
        case 4: return g_wout_aug;
        case 5: return g_w1_aug;
        case 6: return g_w2_aug;
        default: return g_ffn1_aug;
    }
}
__device__ __forceinline__ float* buff(int c, const float* p)
{
    switch (c) {
        case 1: return g_qkv;
        case 2: return g_x1;
        default: return (float*)p;
    }
}
__device__ __forceinline__ void bsplit(float v, __nv_bfloat16& hi, __nv_bfloat16& lo)
{
    hi = __float2bfloat16_rn(v);
    lo = __float2bfloat16_rn(v - __bfloat162float(hi));
}

// ---------------- PTX helpers (baseline PTX; safe on plain sm_103 target) ----
__device__ __forceinline__ uint32_t smem_u32(const void* p)
{
    uint32_t a;
    asm("{ .reg .u64 t; cvta.to.shared.u64 t, %1; cvt.u32.u64 %0, t; }" : "=r"(a) : "l"(p));
    return a;
}
__device__ __forceinline__ void ldm_x4(uint32_t* r, uint32_t a)
{
    asm volatile("ldmatrix.sync.aligned.m8n8.x4.shared.b16 {%0,%1,%2,%3}, [%4];"
        : "=r"(r[0]), "=r"(r[1]), "=r"(r[2]), "=r"(r[3]) : "r"(a));
}
__device__ __forceinline__ void ldm_x4_t(uint32_t* r, uint32_t a)
{
    asm volatile("ldmatrix.sync.aligned.m8n8.x4.trans.shared.b16 {%0,%1,%2,%3}, [%4];"
        : "=r"(r[0]), "=r"(r[1]), "=r"(r[2]), "=r"(r[3]) : "r"(a));
}
__device__ __forceinline__ void mma_bf16(float* c, const uint32_t* a, const uint32_t* b)
{
    asm volatile("mma.sync.aligned.m16n8k16.row.col.f32.bf16.bf16.f32 "
        "{%0,%1,%2,%3}, {%4,%5,%6,%7}, {%8,%9}, {%0,%1,%2,%3};"
        : "+f"(c[0]), "+f"(c[1]), "+f"(c[2]), "+f"(c[3])
        : "r"(a[0]), "r"(a[1]), "r"(a[2]), "r"(a[3]), "r"(b[0]), "r"(b[1]));
}
__device__ __forceinline__ void cpa16(uint32_t s, const void* g)
{
    asm volatile("cp.async.cg.shared.global [%0], [%1], 16;" :: "r"(s), "l"(g));
}
#define CPA_COMMIT() asm volatile("cp.async.commit_group;" ::: "memory")
#define CPA_WAIT(n)  asm volatile("cp.async.wait_group %0;" :: "n"(n) : "memory")

// ---------------- weight split: w[K,N] f32 -> [hi;lo;hi] bf16 ----------------
__global__ __launch_bounds__(256) void split_w_kernel(const float* __restrict__ w,
                                                      int oc, size_t KN)
{
    __nv_bfloat16* out = (__nv_bfloat16*)bufb(oc);
    const size_t i = (size_t)blockIdx.x * 256 + threadIdx.x;
    const float4 v = reinterpret_cast<const float4*>(w)[i];
    __nv_bfloat16 h0, l0, h1, l1, h2, l2, h3, l3;
    bsplit(v.x, h0, l0); bsplit(v.y, h1, l1); bsplit(v.z, h2, l2); bsplit(v.w, h3, l3);
    const size_t e = i * 4;
    __nv_bfloat162 hA, hB, lA, lB;
    hA.x = h0; hA.y = h1; hB.x = h2; hB.y = h3;
    lA.x = l0; lA.y = l1; lB.x = l2; lB.y = l3;
    *(__nv_bfloat162*)&out[e]          = hA; *(__nv_bfloat162*)&out[e + 2]          = hB;
    *(__nv_bfloat162*)&out[KN + e]     = lA; *(__nv_bfloat162*)&out[KN + e + 2]     = lB;
    *(__nv_bfloat162*)&out[2 * KN + e] = hA; *(__nv_bfloat162*)&out[2 * KN + e + 2] = hB;
}

// ---------------- LayerNorm -> augmented bf16 [row, hi|hi|lo] ----------------
__global__ __launch_bounds__(256) void ln_aug_kernel(const float* __restrict__ xp, int xc,
                                                     const float* __restrict__ gam,
                                                     const float* __restrict__ bet)
{
    const float* x = buff(xc, xp);
    __shared__ float sh[8];
    __shared__ float stat[2];
    const int row = blockIdx.x, t = threadIdx.x;

    const float4 v = reinterpret_cast<const float4*>(x)[(size_t)row * 256 + t];
    float s = v.x + v.y + v.z + v.w;
    #pragma unroll
    for (int o = 16; o; o >>= 1) s += __shfl_xor_sync(0xffffffffu, s, o);
    if ((t & 31) == 0) sh[t >> 5] = s;
    __syncthreads();
    if (t < 32) {
        float u = (t < 8) ? sh[t] : 0.f;
        #pragma unroll
        for (int o = 4; o; o >>= 1) u += __shfl_xor_sync(0xffffffffu, u, o);
        if (t == 0) stat[0] = u * (1.f / 1024.f);
    }
    __syncthreads();
    const float mu = stat[0];
    const float a = v.x - mu, b = v.y - mu, c = v.z - mu, d = v.w - mu;
    float s2 = a * a + b * b + c * c + d * d;
    #pragma unroll
    for (int o = 16; o; o >>= 1) s2 += __shfl_xor_sync(0xffffffffu, s2, o);
    if ((t & 31) == 0) sh[t >> 5] = s2;
    __syncthreads();
    if (t < 32) {
        float u = (t < 8) ? sh[t] : 0.f;
        #pragma unroll
        for (int o = 4; o; o >>= 1) u += __shfl_xor_sync(0xffffffffu, u, o);
        if (t == 0) stat[1] = rsqrtf(u * (1.f / 1024.f) + 1e-5f);
    }
    __syncthreads();
    const float inv = stat[1];
    const float4 gv = reinterpret_cast<const float4*>(gam)[t];
    const float4 bv = reinterpret_cast<const float4*>(bet)[t];
    const float o0 = a * inv * gv.x + bv.x, o1 = b * inv * gv.y + bv.y;
    const float o2 = c * inv * gv.z + bv.z, o3 = d * inv * gv.w + bv.w;
    __nv_bfloat16 h0, l0, h1, l1, h2, l2, h3, l3;
    bsplit(o0, h0, l0); bsplit(o1, h1, l1); bsplit(o2, h2, l2); bsplit(o3, h3, l3);
    __nv_bfloat162 hA, hB, lA, lB;
    hA.x = h0; hA.y = h1; hB.x = h2; hB.y = h3;
    lA.x = l0; lA.y = l1; lB.x = l2; lB.y = l3;
    const size_t base = (size_t)row * 3072 + t * 4;
    *(__nv_bfloat162*)&g_ln_aug[base]        = hA; *(__nv_bfloat162*)&g_ln_aug[base + 2]    = hB;
    *(__nv_bfloat162*)&g_ln_aug[base + 1024] = hA; *(__nv_bfloat162*)&g_ln_aug[base + 1026] = hB;
    *(__nv_bfloat162*)&g_ln_aug[base + 2048] = lA; *(__nv_bfloat162*)&g_ln_aug[base + 2050] = lB;
}

// ---------------- HMMA GEMM with cp.async 3-stage pipeline ------------------
// CTA 128x128, BK=32, 256 thr, 8 warps (4m x 2n), warp 32x64 (2x8 m16n8k16).
// Stage = A[128x32] (8KB, chunk swz c^((r>>1)&3)) + B[32x128] (8KB, c^(k&7)).
// 3 stages x 16KB = 48KB static smem. Conflict-free cp.async stores and
// ldmatrix reads (checked per 8-thread phase).
template<bool RELU, bool RESID, bool AUGOUT>
__global__ __launch_bounds__(256) void gemm_mma(
    int N, int KTOT, int Ac, int Bc,
    const float* __restrict__ bias,
    const float* resp, int resc,
    float* Cp, int Cc)
{
    const __nv_bfloat16* A  = bufb(Ac);
    const __nv_bfloat16* Bw = bufb(Bc);
    const float* res = buff(resc, resp);
    float* C = buff(Cc, Cp);

    __shared__ __align__(16) char smem3[3][16384];

    const int tid = threadIdx.x;
    const int wid = tid >> 5, lane = tid & 31;
    const int wm = wid & 3, wn = wid >> 2;
    const int brow = blockIdx.y, bcol = blockIdx.x;

    const __nv_bfloat16* Ablk = A + (size_t)(brow * 128) * KTOT;
    const __nv_bfloat16* Bblk = Bw + bcol * 128;

    const uint32_t smB = smem_u32(smem3);

    // cp.async coords
    const int ar = tid >> 2, acn = tid & 3;     // A: row, chunk (+128 rows via i)
    const int bk = tid >> 4, bcn = tid & 15;    // B: k-row, chunk (+16 k via i)
    const uint32_t aso0 = (uint32_t)(ar * 64  + ((acn ^ ((ar >> 1) & 3)) << 4));
    const uint32_t aso1 = (uint32_t)((ar + 64) * 64 + ((acn ^ (((ar + 64) >> 1) & 3)) << 4));
    const uint32_t bso0 = (uint32_t)(8192 + bk * 256 + ((bcn ^ (bk & 7)) << 4));
    const uint32_t bso1 = (uint32_t)(8192 + (bk + 16) * 256 + ((bcn ^ ((bk + 16) & 7)) << 4));

    // ldmatrix per-lane constants
    const int lr = lane & 15, lc = lane >> 4;
    const int arow[2] = { wm * 32 + lr, wm * 32 + 16 + lr };
    const uint32_t aswz[2] = { (uint32_t)((arow[0] >> 1) & 3), (uint32_t)((arow[1] >> 1) & 3) };
    const uint32_t bswzk = (uint32_t)(lr & 7);

    float acc[2][8][4];
    #pragma unroll
    for (int mt = 0; mt < 2; mt++)
        #pragma unroll
        for (int nt = 0; nt < 8; nt++)
            #pragma unroll
            for (int q = 0; q < 4; q++) acc[mt][nt][q] = 0.f;

    const int NS = KTOT >> 5;

    // issue loads for stage index ss into ring buffer ss%3
    auto issue = [&](int ss) {
        const int kg = ss * 32;
        const uint32_t st = smB + (uint32_t)((ss % 3) * 16384);
        cpa16(st + aso0, Ablk + (size_t)ar * KTOT + kg + acn * 8);
        cpa16(st + aso1, Ablk + (size_t)(ar + 64) * KTOT + kg + acn * 8);
        cpa16(st + bso0, Bblk + (size_t)(kg + bk) * N + bcn * 8);
        cpa16(st + bso1, Bblk + (size_t)(kg + bk + 16) * N + bcn * 8);
        CPA_COMMIT();
    };

    issue(0);
    issue(1);

    #pragma unroll 1
    for (int s = 0; s < NS; s++) {
        if (s + 1 < NS) { CPA_WAIT(1); } else { CPA_WAIT(0); }
        __syncthreads();                   // buffer s visible; compute s-1 retired
        if (s + 2 < NS) issue(s + 2);      // writes buffer (s-1)%3 — safe after sync

        const uint32_t aB = smB + (uint32_t)((s % 3) * 16384);
        const uint32_t bB = aB + 8192;
        #pragma unroll
        for (int ks = 0; ks < 2; ks++) {
            uint32_t af[2][4], bf[4][4];
            #pragma unroll
            for (int mt = 0; mt < 2; mt++) {
                const uint32_t chunk = ((uint32_t)(ks * 2 + lc)) ^ aswz[mt];
                ldm_x4(af[mt], aB + (uint32_t)(arow[mt] * 64) + (chunk << 4));
            }
            const uint32_t kk = (uint32_t)(ks * 16 + lr);
            #pragma unroll
            for (int n16 = 0; n16 < 4; n16++) {
                const uint32_t cn = ((uint32_t)(wn * 8 + n16 * 2 + lc)) ^ bswzk;
                ldm_x4_t(bf[n16], bB + kk * 256 + (cn << 4));
            }
            #pragma unroll
            for (int mt = 0; mt < 2; mt++)
                #pragma unroll
                for (int nt = 0; nt < 8; nt++)
                    mma_bf16(acc[mt][nt], af[mt], &bf[nt >> 1][(nt & 1) * 2]);
        }
    }

    // epilogue (same mapping as validated R6)
    const int rbase = brow * 128 + wm * 32 + (lane >> 2);
    const int cbase = bcol * 128 + wn * 64 + (lane & 3) * 2;
    #pragma unroll
    for (int mt = 0; mt < 2; mt++) {
        #pragma unroll
        for (int nt = 0; nt < 8; nt++) {
            const int c = cbase + nt * 8;
            const float2 bv = *(const float2*)(bias + c);
            #pragma unroll
            for (int hrow = 0; hrow < 2; hrow++) {
                const int r = rbase + mt * 16 + hrow * 8;
                float v0 = acc[mt][nt][hrow * 2]     + bv.x;
                float v1 = acc[mt][nt][hrow * 2 + 1] + bv.y;
                if (AUGOUT) {
                    v0 = fmaxf(v0, 0.f); v1 = fmaxf(v1, 0.f);
                    __nv_bfloat16 h0, l0, h1, l1;
                    bsplit(v0, h0, l0); bsplit(v1, h1, l1);
                    __nv_bfloat162 hp, lp;
                    hp.x = h0; hp.y = h1; lp.x = l0; lp.y = l1;
                    const size_t rb = (size_t)r * 12288 + c;
                    *(__nv_bfloat162*)&g_ffn1_aug[rb]        = hp;
                    *(__nv_bfloat162*)&g_ffn1_aug[rb + 4096] = hp;
                    *(__nv_bfloat162*)&g_ffn1_aug[rb + 8192] = lp;
                } else {
                    const size_t off = (size_t)r * N + c;
                    if (RESID) {
                        const float2 rv = *(const float2*)(res + off);
                        v0 += rv.x; v1 += rv.y;
                    }
                    if (RELU) { v0 = fmaxf(v0, 0.f); v1 = fmaxf(v1, 0.f); }
                    float2 ov; ov.x = v0; ov.y = v1;
                    *(float2*)(C + off) = ov;
                }
            }
        }
    }
}

// ---------------- windowed flash attention (fp32) -> g_ctx_aug ----------------
__global__ __launch_bounds__(256) void attn_kernel(const float* __restrict__ res_pos)
{
    const float* qkv = g_qkv;
    __shared__ float Qs [64 * 64];
    __shared__ float KtS[64 * 64];
    __shared__ float Vs [64 * 64];
    float* P = KtS;

    const int qt = blockIdx.x, h = blockIdx.y, bb = blockIdx.z;
    const int q0 = qt * 64, tid = threadIdx.x;
    const int tx = tid & 15, ty = tid >> 4;
    const int row0 = ty * 4, col0 = tx * 4;

    const float* qbase = qkv + ((size_t)(bb * 2048 + q0)) * 3072 + h * 64;
    #pragma unroll
    for (int it = 0; it < 16; it++) {
        const int idx = it * 256 + tid;
        const int r = idx >> 6, d = idx & 63;
        Qs[r * 64 + d] = qbase[(size_t)r * 3072 + d];
    }

    float m_i[4], l_i[4], oo[4][4];
    #pragma unroll
    for (int i = 0; i < 4; i++) {
        m_i[i] = -1e30f; l_i[i] = 0.f;
        #pragma unroll
        for (int j = 0; j < 4; j++) oo[i][j] = 0.f;
    }

    int lo = q0 - 511; if (lo < 0) lo = 0;
    for (int kt = lo >> 6; kt <= qt; kt++) {
        __syncthreads();
        const float* kbase = qkv + ((size_t)(bb * 2048 + kt * 64)) * 3072 + 1024 + h * 64;
        const float* vbase = kbase + 1024;
        #pragma unroll
        for (int it = 0; it < 16; it++) {
            const int idx = it * 256 + tid;
            const int c = idx >> 6, d = idx & 63;
            KtS[d * 64 + (c ^ (d & 28))] = kbase[(size_t)c * 3072 + d];
            Vs[c * 64 + d]               = vbase[(size_t)c * 3072 + d];
        }
        __syncthreads();

        float s[4][4];
        #pragma unroll
        for (int i = 0; i < 4; i++)
            #pragma unroll
            for (int j = 0; j < 4; j++) s[i][j] = 0.f;
        for (int d0 = 0; d0 < 64; d0 += 4) {
            float qv[4][4];
            #pragma unroll
            for (int i = 0; i < 4; i++)
                *(float4*)qv[i] = *(const float4*)&Qs[(row0 + i) * 64 + d0];
            #pragma unroll
            for (int dd = 0; dd < 4; dd++) {
                const int d = d0 + dd;
                float kv[4];
                *(float4*)kv = *(const float4*)&KtS[d * 64 + (col0 ^ (d & 28))];
                #pragma unroll
                for (int i = 0; i < 4; i++)
                    #pragma unroll
                    for (int j = 0; j < 4; j++)
                        s[i][j] = fmaf(qv[i][dd], kv[j], s[i][j]);
            }
        }
        #pragma unroll
        for (int i = 0; i < 4; i++) {
            const int q = q0 + row0 + i;
            #pragma unroll
            for (int j = 0; j < 4; j++) {
                const int dd = q - (kt * 64 + col0 + j);
                s[i][j] = (dd >= 0 && dd < 512)
                        ? s[i][j] * 0.125f + __ldg(&res_pos[h * 512 + dd]) : -1e30f;
            }
        }
        #pragma unroll
        for (int i = 0; i < 4; i++) {
            float mt = fmaxf(fmaxf(s[i][0], s[i][1]), fmaxf(s[i][2], s[i][3]));
            #pragma unroll
            for (int o = 8; o; o >>= 1) mt = fmaxf(mt, __shfl_xor_sync(0xffffffffu, mt, o));
            const float mn = fmaxf(m_i[i], mt);
            const float alpha = __expf(m_i[i] - mn);
            m_i[i] = mn;
            float rs = 0.f;
            #pragma unroll
            for (int j = 0; j < 4; j++) { s[i][j] = __expf(s[i][j] - mn); rs += s[i][j]; }
            #pragma unroll
            for (int o = 8; o; o >>= 1) rs += __shfl_xor_sync(0xffffffffu, rs, o);
            l_i[i] = l_i[i] * alpha + rs;
            #pragma unroll
            for (int j = 0; j < 4; j++) oo[i][j] *= alpha;
        }
        __syncthreads();
        #pragma unroll
        for (int i = 0; i < 4; i++) {
            const int r = row0 + i;
            float4 pv;
            pv.x = s[i][0]; pv.y = s[i][1]; pv.z = s[i][2]; pv.w = s[i][3];
            *(float4*)&P[r * 64 + (col0 ^ (r & 28))] = pv;
        }
        __syncthreads();
        #pragma unroll 4
        for (int kk = 0; kk < 64; kk++) {
            float ar[4], bc[4];
            #pragma unroll
            for (int i = 0; i < 4; i++) ar[i] = P[(row0 + i) * 64 + (kk ^ ((row0 + i) & 28))];
            *(float4*)bc = *(const float4*)&Vs[kk * 64 + col0];
            #pragma unroll
            for (int i = 0; i < 4; i++)
                #pragma unroll
                for (int j = 0; j < 4; j++)
                    oo[i][j] = fmaf(ar[i], bc[j], oo[i][j]);
        }
    }

    #pragma unroll
    for (int i = 0; i < 4; i++) {
        const float rl = 1.f / l_i[i];
        const size_t base = ((size_t)(bb * 2048 + q0 + row0 + i)) * 3072 + h * 64 + col0;
        __nv_bfloat16 h0, l0h, h1, l1h, h2, l2h, h3, l3h;
        bsplit(oo[i][0] * rl, h0, l0h); bsplit(oo[i][1] * rl, h1, l1h);
        bsplit(oo[i][2] * rl, h2, l2h); bsplit(oo[i][3] * rl, h3, l3h);
        __nv_bfloat162 hA, hB, lA, lB;
        hA.x = h0; hA.y = h1; hB.x = h2; hB.y = h3;
        lA.x = l0h; lA.y = l1h; lB.x = l2h; lB.y = l3h;
        *(__nv_bfloat162*)&g_ctx_aug[base]        = hA; *(__nv_bfloat162*)&g_ctx_aug[base + 2]    = hB;
        *(__nv_bfloat162*)&g_ctx_aug[base + 1024] = hA; *(__nv_bfloat162*)&g_ctx_aug[base + 1026] = hB;
        *(__nv_bfloat162*)&g_ctx_aug[base + 2048] = lA; *(__nv_bfloat162*)&g_ctx_aug[base + 2050] = lB;
    }
}

// ---------------- launch: kernel launches ONLY ----------------
extern "C" void kernel_launch(void* const* d_in, const int* in_sizes, int n_in,
                              void* d_out, int out_size)
{
    (void)in_sizes; (void)n_in; (void)out_size;
    const float* x      = (const float*)d_in[0];
    const float* respos = (const float*)d_in[1];
    const float* w_qkv  = (const float*)d_in[2];
    const float* b_qkv  = (const float*)d_in[3];
    const float* w_out  = (const float*)d_in[4];
    const float* b_out  = (const float*)d_in[5];
    const float* w1     = (const float*)d_in[6];
    const float* b1     = (const float*)d_in[7];
    const float* w2     = (const float*)d_in[8];
    const float* b2     = (const float*)d_in[9];
    const float* ln1_g  = (const float*)d_in[10];
    const float* ln1_b  = (const float*)d_in[11];
    const float* ln2_g  = (const float*)d_in[12];
    const float* ln2_b  = (const float*)d_in[13];
    float* out = (float*)d_out;

    split_w_kernel<<<3072, 256>>>(w_qkv, 3, (size_t)1024 * 3072);
    split_w_kernel<<<1024, 256>>>(w_out, 4, (size_t)1024 * 1024);
    split_w_kernel<<<4096, 256>>>(w1,    5, (size_t)1024 * 4096);
    split_w_kernel<<<4096, 256>>>(w2,    6, (size_t)4096 * 1024);

    ln_aug_kernel<<<MROWS, 256>>>(x, 0, ln1_g, ln1_b);
    gemm_mma<false, false, false><<<dim3(24, 32), 256>>>(
        3072, 3072, 1, 3, b_qkv, nullptr, 0, nullptr, 1);
    attn_kernel<<<dim3(32, 16, 2), 256>>>(respos);
    gemm_mma<false, true, false><<<dim3(8, 32), 256>>>(
        1024, 3072, 2, 4, b_out, x, 0, nullptr, 2);
    ln_aug_kernel<<<MROWS, 256>>>(nullptr, 2, ln2_g, ln2_b);
    gemm_mma<true, false, true><<<dim3(32, 32), 256>>>(
        4096, 3072, 1, 5, b1, nullptr, 0, nullptr, 0);
    gemm_mma<false, true, false><<<dim3(8, 32), 256>>>(
        1024, 12288, 7, 6, b2, nullptr, 2, out, 0);
}

// round 8
// speedup vs baseline: 3.8899x; 1.8552x over previous
#include <cuda_runtime.h>
#include <cuda_fp16.h>
#include <stdint.h>
#include <math.h>

#define MROWS 4096

// ---------------- scratch (fp16 single-precision operands) ----------------
__device__ __half g_ln  [(size_t)MROWS * 1024];
__device__ __half g_ctx [(size_t)MROWS * 1024];
__device__ __half g_wqkv[(size_t)1024 * 3072];
__device__ __half g_wout[(size_t)1024 * 1024];
__device__ __half g_w1  [(size_t)1024 * 4096];
__device__ __half g_w2  [(size_t)4096 * 1024];
__device__ __half g_ffn1[(size_t)MROWS * 4096];
__device__ float  g_qkv [(size_t)MROWS * 3072];
__device__ float  g_x1  [(size_t)MROWS * 1024];

__device__ __forceinline__ const __half* bufh(int c)
{
    switch (c) {
        case 1: return g_ln;
        case 2: return g_ctx;
        case 3: return g_wqkv;
        case 4: return g_wout;
        case 5: return g_w1;
        case 6: return g_w2;
        default: return g_ffn1;
    }
}
__device__ __forceinline__ float* buff(int c, const float* p)
{
    switch (c) {
        case 1: return g_qkv;
        case 2: return g_x1;
        default: return (float*)p;
    }
}

// ---------------- PTX helpers (baseline PTX; safe on plain sm_103) ----------
__device__ __forceinline__ uint32_t smem_u32(const void* p)
{
    uint32_t a;
    asm("{ .reg .u64 t; cvta.to.shared.u64 t, %1; cvt.u32.u64 %0, t; }" : "=r"(a) : "l"(p));
    return a;
}
__device__ __forceinline__ void ldm_x4(uint32_t* r, uint32_t a)
{
    asm volatile("ldmatrix.sync.aligned.m8n8.x4.shared.b16 {%0,%1,%2,%3}, [%4];"
        : "=r"(r[0]), "=r"(r[1]), "=r"(r[2]), "=r"(r[3]) : "r"(a));
}
__device__ __forceinline__ void ldm_x4_t(uint32_t* r, uint32_t a)
{
    asm volatile("ldmatrix.sync.aligned.m8n8.x4.trans.shared.b16 {%0,%1,%2,%3}, [%4];"
        : "=r"(r[0]), "=r"(r[1]), "=r"(r[2]), "=r"(r[3]) : "r"(a));
}
__device__ __forceinline__ void mma_f16(float* c, const uint32_t* a, const uint32_t* b)
{
    asm volatile("mma.sync.aligned.m16n8k16.row.col.f32.f16.f16.f32 "
        "{%0,%1,%2,%3}, {%4,%5,%6,%7}, {%8,%9}, {%0,%1,%2,%3};"
        : "+f"(c[0]), "+f"(c[1]), "+f"(c[2]), "+f"(c[3])
        : "r"(a[0]), "r"(a[1]), "r"(a[2]), "r"(a[3]), "r"(b[0]), "r"(b[1]));
}
__device__ __forceinline__ void cpa16(uint32_t s, const void* g)
{
    asm volatile("cp.async.cg.shared.global [%0], [%1], 16;" :: "r"(s), "l"(g));
}
#define CPA_COMMIT() asm volatile("cp.async.commit_group;" ::: "memory")
#define CPA_WAIT(n)  asm volatile("cp.async.wait_group %0;" :: "n"(n) : "memory")

// ---------------- weight cast: f32 -> f16 ----------------
__global__ __launch_bounds__(256) void cast_w_kernel(const float* __restrict__ w, int oc)
{
    __half* out = (__half*)bufh(oc);
    const size_t i = (size_t)blockIdx.x * 256 + threadIdx.x;
    const float4 v = reinterpret_cast<const float4*>(w)[i];
    __half2 a = __floats2half2_rn(v.x, v.y);
    __half2 b = __floats2half2_rn(v.z, v.w);
    *(__half2*)&out[i * 4]     = a;
    *(__half2*)&out[i * 4 + 2] = b;
}

// ---------------- LayerNorm -> fp16 [row, 1024] ----------------
__global__ __launch_bounds__(256) void ln_h_kernel(const float* __restrict__ xp, int xc,
                                                   const float* __restrict__ gam,
                                                   const float* __restrict__ bet)
{
    const float* x = buff(xc, xp);
    __shared__ float sh[8];
    __shared__ float stat[2];
    const int row = blockIdx.x, t = threadIdx.x;

    const float4 v = reinterpret_cast<const float4*>(x)[(size_t)row * 256 + t];
    float s = v.x + v.y + v.z + v.w;
    #pragma unroll
    for (int o = 16; o; o >>= 1) s += __shfl_xor_sync(0xffffffffu, s, o);
    if ((t & 31) == 0) sh[t >> 5] = s;
    __syncthreads();
    if (t < 32) {
        float u = (t < 8) ? sh[t] : 0.f;
        #pragma unroll
        for (int o = 4; o; o >>= 1) u += __shfl_xor_sync(0xffffffffu, u, o);
        if (t == 0) stat[0] = u * (1.f / 1024.f);
    }
    __syncthreads();
    const float mu = stat[0];
    const float a = v.x - mu, b = v.y - mu, c = v.z - mu, d = v.w - mu;
    float s2 = a * a + b * b + c * c + d * d;
    #pragma unroll
    for (int o = 16; o; o >>= 1) s2 += __shfl_xor_sync(0xffffffffu, s2, o);
    if ((t & 31) == 0) sh[t >> 5] = s2;
    __syncthreads();
    if (t < 32) {
        float u = (t < 8) ? sh[t] : 0.f;
        #pragma unroll
        for (int o = 4; o; o >>= 1) u += __shfl_xor_sync(0xffffffffu, u, o);
        if (t == 0) stat[1] = rsqrtf(u * (1.f / 1024.f) + 1e-5f);
    }
    __syncthreads();
    const float inv = stat[1];
    const float4 gv = reinterpret_cast<const float4*>(gam)[t];
    const float4 bv = reinterpret_cast<const float4*>(bet)[t];
    const float o0 = a * inv * gv.x + bv.x, o1 = b * inv * gv.y + bv.y;
    const float o2 = c * inv * gv.z + bv.z, o3 = d * inv * gv.w + bv.w;
    const size_t base = (size_t)row * 1024 + t * 4;
    *(__half2*)&g_ln[base]     = __floats2half2_rn(o0, o1);
    *(__half2*)&g_ln[base + 2] = __floats2half2_rn(o2, o3);
}

// ---------------- HMMA fp16 GEMM with cp.async 3-stage pipeline --------------
// CTA 128x128, BK=32, 256 thr, 8 warps (4m x 2n), warp 32x64 (2x8 m16n8k16).
// Stage = A[128x32] (8KB, chunk swz c^((r>>1)&3)) + B[32x128] (8KB, c^(k&7)).
template<bool RELU, bool RESID, bool HALFOUT>
__global__ __launch_bounds__(256) void gemm_mma(
    int N, int KTOT, int Ac, int Bc,
    const float* __restrict__ bias,
    const float* resp, int resc,
    float* Cp, int Cc)
{
    const __half* A  = bufh(Ac);
    const __half* Bw = bufh(Bc);
    const float* res = buff(resc, resp);
    float* C = buff(Cc, Cp);

    __shared__ __align__(16) char smem3[3][16384];

    const int tid = threadIdx.x;
    const int wid = tid >> 5, lane = tid & 31;
    const int wm = wid & 3, wn = wid >> 2;
    const int brow = blockIdx.y, bcol = blockIdx.x;

    const __half* Ablk = A + (size_t)(brow * 128) * KTOT;
    const __half* Bblk = Bw + bcol * 128;

    const uint32_t smB = smem_u32(smem3);

    const int ar = tid >> 2, acn = tid & 3;
    const int bk = tid >> 4, bcn = tid & 15;
    const uint32_t aso0 = (uint32_t)(ar * 64  + ((acn ^ ((ar >> 1) & 3)) << 4));
    const uint32_t aso1 = (uint32_t)((ar + 64) * 64 + ((acn ^ (((ar + 64) >> 1) & 3)) << 4));
    const uint32_t bso0 = (uint32_t)(8192 + bk * 256 + ((bcn ^ (bk & 7)) << 4));
    const uint32_t bso1 = (uint32_t)(8192 + (bk + 16) * 256 + ((bcn ^ ((bk + 16) & 7)) << 4));

    const int lr = lane & 15, lc = lane >> 4;
    const int arow[2] = { wm * 32 + lr, wm * 32 + 16 + lr };
    const uint32_t aswz[2] = { (uint32_t)((arow[0] >> 1) & 3), (uint32_t)((arow[1] >> 1) & 3) };
    const uint32_t bswzk = (uint32_t)(lr & 7);

    float acc[2][8][4];
    #pragma unroll
    for (int mt = 0; mt < 2; mt++)
        #pragma unroll
        for (int nt = 0; nt < 8; nt++)
            #pragma unroll
            for (int q = 0; q < 4; q++) acc[mt][nt][q] = 0.f;

    const int NS = KTOT >> 5;

    auto issue = [&](int ss) {
        const int kg = ss * 32;
        const uint32_t st = smB + (uint32_t)((ss % 3) * 16384);
        cpa16(st + aso0, Ablk + (size_t)ar * KTOT + kg + acn * 8);
        cpa16(st + aso1, Ablk + (size_t)(ar + 64) * KTOT + kg + acn * 8);
        cpa16(st + bso0, Bblk + (size_t)(kg + bk) * N + bcn * 8);
        cpa16(st + bso1, Bblk + (size_t)(kg + bk + 16) * N + bcn * 8);
        CPA_COMMIT();
    };

    issue(0);
    issue(1);

    #pragma unroll 1
    for (int s = 0; s < NS; s++) {
        if (s + 1 < NS) { CPA_WAIT(1); } else { CPA_WAIT(0); }
        __syncthreads();
        if (s + 2 < NS) issue(s + 2);

        const uint32_t aB = smB + (uint32_t)((s % 3) * 16384);
        const uint32_t bB = aB + 8192;
        #pragma unroll
        for (int ks = 0; ks < 2; ks++) {
            uint32_t af[2][4], bf[4][4];
            #pragma unroll
            for (int mt = 0; mt < 2; mt++) {
                const uint32_t chunk = ((uint32_t)(ks * 2 + lc)) ^ aswz[mt];
                ldm_x4(af[mt], aB + (uint32_t)(arow[mt] * 64) + (chunk << 4));
            }
            const uint32_t kk = (uint32_t)(ks * 16 + lr);
            #pragma unroll
            for (int n16 = 0; n16 < 4; n16++) {
                const uint32_t cn = ((uint32_t)(wn * 8 + n16 * 2 + lc)) ^ bswzk;
                ldm_x4_t(bf[n16], bB + kk * 256 + (cn << 4));
            }
            #pragma unroll
            for (int mt = 0; mt < 2; mt++)
                #pragma unroll
                for (int nt = 0; nt < 8; nt++)
                    mma_f16(acc[mt][nt], af[mt], &bf[nt >> 1][(nt & 1) * 2]);
        }
    }

    const int rbase = brow * 128 + wm * 32 + (lane >> 2);
    const int cbase = bcol * 128 + wn * 64 + (lane & 3) * 2;
    #pragma unroll
    for (int mt = 0; mt < 2; mt++) {
        #pragma unroll
        for (int nt = 0; nt < 8; nt++) {
            const int c = cbase + nt * 8;
            const float2 bv = *(const float2*)(bias + c);
            #pragma unroll
            for (int hrow = 0; hrow < 2; hrow++) {
                const int r = rbase + mt * 16 + hrow * 8;
                float v0 = acc[mt][nt][hrow * 2]     + bv.x;
                float v1 = acc[mt][nt][hrow * 2 + 1] + bv.y;
                if (HALFOUT) {
                    v0 = fmaxf(v0, 0.f); v1 = fmaxf(v1, 0.f);
                    *(__half2*)&g_ffn1[(size_t)r * 4096 + c] = __floats2half2_rn(v0, v1);
                } else {
                    const size_t off = (size_t)r * N + c;
                    if (RESID) {
                        const float2 rv = *(const float2*)(res + off);
                        v0 += rv.x; v1 += rv.y;
                    }
                    if (RELU) { v0 = fmaxf(v0, 0.f); v1 = fmaxf(v1, 0.f); }
                    float2 ov; ov.x = v0; ov.y = v1;
                    *(float2*)(C + off) = ov;
                }
            }
        }
    }
}

// ---------------- windowed flash attention (fp32) -> g_ctx (fp16) -----------
__global__ __launch_bounds__(256) void attn_kernel(const float* __restrict__ res_pos)
{
    const float* qkv = g_qkv;
    __shared__ float Qs [64 * 64];
    __shared__ float KtS[64 * 64];
    __shared__ float Vs [64 * 64];
    float* P = KtS;

    const int qt = blockIdx.x, h = blockIdx.y, bb = blockIdx.z;
    const int q0 = qt * 64, tid = threadIdx.x;
    const int tx = tid & 15, ty = tid >> 4;
    const int row0 = ty * 4, col0 = tx * 4;

    const float* qbase = qkv + ((size_t)(bb * 2048 + q0)) * 3072 + h * 64;
    #pragma unroll
    for (int it = 0; it < 16; it++) {
        const int idx = it * 256 + tid;
        const int r = idx >> 6, d = idx & 63;
        Qs[r * 64 + d] = qbase[(size_t)r * 3072 + d];
    }

    float m_i[4], l_i[4], oo[4][4];
    #pragma unroll
    for (int i = 0; i < 4; i++) {
        m_i[i] = -1e30f; l_i[i] = 0.f;
        #pragma unroll
        for (int j = 0; j < 4; j++) oo[i][j] = 0.f;
    }

    int lo = q0 - 511; if (lo < 0) lo = 0;
    for (int kt = lo >> 6; kt <= qt; kt++) {
        __syncthreads();
        const float* kbase = qkv + ((size_t)(bb * 2048 + kt * 64)) * 3072 + 1024 + h * 64;
        const float* vbase = kbase + 1024;
        #pragma unroll
        for (int it = 0; it < 16; it++) {
            const int idx = it * 256 + tid;
            const int c = idx >> 6, d = idx & 63;
            KtS[d * 64 + (c ^ (d & 28))] = kbase[(size_t)c * 3072 + d];
            Vs[c * 64 + d]               = vbase[(size_t)c * 3072 + d];
        }
        __syncthreads();

        float s[4][4];
        #pragma unroll
        for (int i = 0; i < 4; i++)
            #pragma unroll
            for (int j = 0; j < 4; j++) s[i][j] = 0.f;
        for (int d0 = 0; d0 < 64; d0 += 4) {
            float qv[4][4];
            #pragma unroll
            for (int i = 0; i < 4; i++)
                *(float4*)qv[i] = *(const float4*)&Qs[(row0 + i) * 64 + d0];
            #pragma unroll
            for (int dd = 0; dd < 4; dd++) {
                const int d = d0 + dd;
                float kv[4];
                *(float4*)kv = *(const float4*)&KtS[d * 64 + (col0 ^ (d & 28))];
                #pragma unroll
                for (int i = 0; i < 4; i++)
                    #pragma unroll
                    for (int j = 0; j < 4; j++)
                        s[i][j] = fmaf(qv[i][dd], kv[j], s[i][j]);
            }
        }
        #pragma unroll
        for (int i = 0; i < 4; i++) {
            const int q = q0 + row0 + i;
            #pragma unroll
            for (int j = 0; j < 4; j++) {
                const int dd = q - (kt * 64 + col0 + j);
                s[i][j] = (dd >= 0 && dd < 512)
                        ? s[i][j] * 0.125f + __ldg(&res_pos[h * 512 + dd]) : -1e30f;
            }
        }
        #pragma unroll
        for (int i = 0; i < 4; i++) {
            float mt = fmaxf(fmaxf(s[i][0], s[i][1]), fmaxf(s[i][2], s[i][3]));
            #pragma unroll
            for (int o = 8; o; o >>= 1) mt = fmaxf(mt, __shfl_xor_sync(0xffffffffu, mt, o));
            const float mn = fmaxf(m_i[i], mt);
            const float alpha = __expf(m_i[i] - mn);
            m_i[i] = mn;
            float rs = 0.f;
            #pragma unroll
            for (int j = 0; j < 4; j++) { s[i][j] = __expf(s[i][j] - mn); rs += s[i][j]; }
            #pragma unroll
            for (int o = 8; o; o >>= 1) rs += __shfl_xor_sync(0xffffffffu, rs, o);
            l_i[i] = l_i[i] * alpha + rs;
            #pragma unroll
            for (int j = 0; j < 4; j++) oo[i][j] *= alpha;
        }
        __syncthreads();
        #pragma unroll
        for (int i = 0; i < 4; i++) {
            const int r = row0 + i;
            float4 pv;
            pv.x = s[i][0]; pv.y = s[i][1]; pv.z = s[i][2]; pv.w = s[i][3];
            *(float4*)&P[r * 64 + (col0 ^ (r & 28))] = pv;
        }
        __syncthreads();
        #pragma unroll 4
        for (int kk = 0; kk < 64; kk++) {
            float ar[4], bc[4];
            #pragma unroll
            for (int i = 0; i < 4; i++) ar[i] = P[(row0 + i) * 64 + (kk ^ ((row0 + i) & 28))];
            *(float4*)bc = *(const float4*)&Vs[kk * 64 + col0];
            #pragma unroll
            for (int i = 0; i < 4; i++)
                #pragma unroll
                for (int j = 0; j < 4; j++)
                    oo[i][j] = fmaf(ar[i], bc[j], oo[i][j]);
        }
    }

    #pragma unroll
    for (int i = 0; i < 4; i++) {
        const float rl = 1.f / l_i[i];
        const size_t base = ((size_t)(bb * 2048 + q0 + row0 + i)) * 1024 + h * 64 + col0;
        *(__half2*)&g_ctx[base]     = __floats2half2_rn(oo[i][0] * rl, oo[i][1] * rl);
        *(__half2*)&g_ctx[base + 2] = __floats2half2_rn(oo[i][2] * rl, oo[i][3] * rl);
    }
}

// ---------------- launch: kernel launches ONLY ----------------
extern "C" void kernel_launch(void* const* d_in, const int* in_sizes, int n_in,
                              void* d_out, int out_size)
{
    (void)in_sizes; (void)n_in; (void)out_size;
    const float* x      = (const float*)d_in[0];
    const float* respos = (const float*)d_in[1];
    const float* w_qkv  = (const float*)d_in[2];
    const float* b_qkv  = (const float*)d_in[3];
    const float* w_out  = (const float*)d_in[4];
    const float* b_out  = (const float*)d_in[5];
    const float* w1     = (const float*)d_in[6];
    const float* b1     = (const float*)d_in[7];
    const float* w2     = (const float*)d_in[8];
    const float* b2     = (const float*)d_in[9];
    const float* ln1_g  = (const float*)d_in[10];
    const float* ln1_b  = (const float*)d_in[11];
    const float* ln2_g  = (const float*)d_in[12];
    const float* ln2_b  = (const float*)d_in[13];
    float* out = (float*)d_out;

    // weight casts f32 -> f16
    cast_w_kernel<<<3072, 256>>>(w_qkv, 3);
    cast_w_kernel<<<1024, 256>>>(w_out, 4);
    cast_w_kernel<<<4096, 256>>>(w1,    5);
    cast_w_kernel<<<4096, 256>>>(w2,    6);

    // 1. ln1 -> g_ln (fp16)
    ln_h_kernel<<<MROWS, 256>>>(x, 0, ln1_g, ln1_b);
    // 2. qkv = ln1 @ wqkv + b_qkv -> g_qkv (fp32)
    gemm_mma<false, false, false><<<dim3(24, 32), 256>>>(
        3072, 1024, 1, 3, b_qkv, nullptr, 0, nullptr, 1);
    // 3. attention -> g_ctx (fp16)
    attn_kernel<<<dim3(32, 16, 2), 256>>>(respos);
    // 4. x1 = x + ctx @ wout + b_out -> g_x1
    gemm_mma<false, true, false><<<dim3(8, 32), 256>>>(
        1024, 1024, 2, 4, b_out, x, 0, nullptr, 2);
    // 5. ln2 -> g_ln
    ln_h_kernel<<<MROWS, 256>>>(nullptr, 2, ln2_g, ln2_b);
    // 6. ffn1 = relu(ln2 @ w1 + b1) -> g_ffn1 (fp16 epilogue)
    gemm_mma<true, false, true><<<dim3(32, 32), 256>>>(
        4096, 1024, 1, 5, b1, nullptr, 0, nullptr, 0);
    // 7. out = x1 + ffn1 @ w2 + b2 -> d_out
    gemm_mma<false, true, false><<<dim3(8, 32), 256>>>(
        1024, 4096, 7, 6, b2, nullptr, 2, out, 0);
}

// round 9
// speedup vs baseline: 6.2554x; 1.6081x over previous
#include <cuda_runtime.h>
#include <cuda_fp16.h>
#include <stdint.h>
#include <math.h>

#define MROWS 4096

// ---------------- scratch (fp16 operands) ----------------
__device__ __half g_ln  [(size_t)MROWS * 1024];
__device__ __half g_ctx [(size_t)MROWS * 1024];
__device__ __half g_wqkv[(size_t)1024 * 3072];
__device__ __half g_wout[(size_t)1024 * 1024];
__device__ __half g_w1  [(size_t)1024 * 4096];
__device__ __half g_w2  [(size_t)4096 * 1024];
__device__ __half g_ffn1[(size_t)MROWS * 4096];
__device__ __half g_qkvh[(size_t)MROWS * 3072];
__device__ float  g_x1  [(size_t)MROWS * 1024];

__device__ __forceinline__ const __half* bufh(int c)
{
    switch (c) {
        case 1: return g_ln;
        case 2: return g_ctx;
        case 3: return g_wqkv;
        case 4: return g_wout;
        case 5: return g_w1;
        case 6: return g_w2;
        case 7: return g_ffn1;
        default: return g_qkvh;
    }
}
__device__ __forceinline__ float* buff(int c, const float* p)
{
    switch (c) {
        case 2: return g_x1;
        default: return (float*)p;
    }
}

// ---------------- PTX helpers (baseline PTX; safe on plain sm_103) ----------
__device__ __forceinline__ uint32_t smem_u32(const void* p)
{
    uint32_t a;
    asm("{ .reg .u64 t; cvta.to.shared.u64 t, %1; cvt.u32.u64 %0, t; }" : "=r"(a) : "l"(p));
    return a;
}
__device__ __forceinline__ void ldm_x4(uint32_t* r, uint32_t a)
{
    asm volatile("ldmatrix.sync.aligned.m8n8.x4.shared.b16 {%0,%1,%2,%3}, [%4];"
        : "=r"(r[0]), "=r"(r[1]), "=r"(r[2]), "=r"(r[3]) : "r"(a));
}
__device__ __forceinline__ void ldm_x4_t(uint32_t* r, uint32_t a)
{
    asm volatile("ldmatrix.sync.aligned.m8n8.x4.trans.shared.b16 {%0,%1,%2,%3}, [%4];"
        : "=r"(r[0]), "=r"(r[1]), "=r"(r[2]), "=r"(r[3]) : "r"(a));
}
__device__ __forceinline__ void mma_f16(float* c, const uint32_t* a, const uint32_t* b)
{
    asm volatile("mma.sync.aligned.m16n8k16.row.col.f32.f16.f16.f32 "
        "{%0,%1,%2,%3}, {%4,%5,%6,%7}, {%8,%9}, {%0,%1,%2,%3};"
        : "+f"(c[0]), "+f"(c[1]), "+f"(c[2]), "+f"(c[3])
        : "r"(a[0]), "r"(a[1]), "r"(a[2]), "r"(a[3]), "r"(b[0]), "r"(b[1]));
}
__device__ __forceinline__ void cpa16(uint32_t s, const void* g)
{
    asm volatile("cp.async.cg.shared.global [%0], [%1], 16;" :: "r"(s), "l"(g));
}
#define CPA_COMMIT() asm volatile("cp.async.commit_group;" ::: "memory")
#define CPA_WAIT(n)  asm volatile("cp.async.wait_group %0;" :: "n"(n) : "memory")

// ---------------- weight cast: f32 -> f16 ----------------
__global__ __launch_bounds__(256) void cast_w_kernel(const float* __restrict__ w, int oc)
{
    __half* out = (__half*)bufh(oc);
    const size_t i = (size_t)blockIdx.x * 256 + threadIdx.x;
    const float4 v = reinterpret_cast<const float4*>(w)[i];
    *(__half2*)&out[i * 4]     = __floats2half2_rn(v.x, v.y);
    *(__half2*)&out[i * 4 + 2] = __floats2half2_rn(v.z, v.w);
}

// ---------------- LayerNorm -> fp16 [row, 1024] ----------------
__global__ __launch_bounds__(256) void ln_h_kernel(const float* __restrict__ xp, int xc,
                                                   const float* __restrict__ gam,
                                                   const float* __restrict__ bet)
{
    const float* x = buff(xc, xp);
    __shared__ float sh[8];
    __shared__ float stat[2];
    const int row = blockIdx.x, t = threadIdx.x;

    const float4 v = reinterpret_cast<const float4*>(x)[(size_t)row * 256 + t];
    float s = v.x + v.y + v.z + v.w;
    #pragma unroll
    for (int o = 16; o; o >>= 1) s += __shfl_xor_sync(0xffffffffu, s, o);
    if ((t & 31) == 0) sh[t >> 5] = s;
    __syncthreads();
    if (t < 32) {
        float u = (t < 8) ? sh[t] : 0.f;
        #pragma unroll
        for (int o = 4; o; o >>= 1) u += __shfl_xor_sync(0xffffffffu, u, o);
        if (t == 0) stat[0] = u * (1.f / 1024.f);
    }
    __syncthreads();
    const float mu = stat[0];
    const float a = v.x - mu, b = v.y - mu, c = v.z - mu, d = v.w - mu;
    float s2 = a * a + b * b + c * c + d * d;
    #pragma unroll
    for (int o = 16; o; o >>= 1) s2 += __shfl_xor_sync(0xffffffffu, s2, o);
    if ((t & 31) == 0) sh[t >> 5] = s2;
    __syncthreads();
    if (t < 32) {
        float u = (t < 8) ? sh[t] : 0.f;
        #pragma unroll
        for (int o = 4; o; o >>= 1) u += __shfl_xor_sync(0xffffffffu, u, o);
        if (t == 0) stat[1] = rsqrtf(u * (1.f / 1024.f) + 1e-5f);
    }
    __syncthreads();
    const float inv = stat[1];
    const float4 gv = reinterpret_cast<const float4*>(gam)[t];
    const float4 bv = reinterpret_cast<const float4*>(bet)[t];
    const float o0 = a * inv * gv.x + bv.x, o1 = b * inv * gv.y + bv.y;
    const float o2 = c * inv * gv.z + bv.z, o3 = d * inv * gv.w + bv.w;
    const size_t base = (size_t)row * 1024 + t * 4;
    *(__half2*)&g_ln[base]     = __floats2half2_rn(o0, o1);
    *(__half2*)&g_ln[base + 2] = __floats2half2_rn(o2, o3);
}

// ---------------- HMMA fp16 GEMM (cp.async 3-stage), optional fp16 out -------
template<bool RELU, bool RESID, bool HALFOUT>
__global__ __launch_bounds__(256) void gemm_mma(
    int N, int KTOT, int Ac, int Bc,
    const float* __restrict__ bias,
    const float* resp, int resc,
    float* Cp, int Cc)
{
    const __half* A  = bufh(Ac);
    const __half* Bw = bufh(Bc);
    const float* res = buff(resc, resp);
    float* C = HALFOUT ? nullptr : buff(Cc, Cp);
    __half* Ch = HALFOUT ? (__half*)bufh(Cc) : nullptr;

    __shared__ __align__(16) char smem3[3][16384];

    const int tid = threadIdx.x;
    const int wid = tid >> 5, lane = tid & 31;
    const int wm = wid & 3, wn = wid >> 2;
    const int brow = blockIdx.y, bcol = blockIdx.x;

    const __half* Ablk = A + (size_t)(brow * 128) * KTOT;
    const __half* Bblk = Bw + bcol * 128;

    const uint32_t smB = smem_u32(smem3);

    const int ar = tid >> 2, acn = tid & 3;
    const int bk = tid >> 4, bcn = tid & 15;
    const uint32_t aso0 = (uint32_t)(ar * 64  + ((acn ^ ((ar >> 1) & 3)) << 4));
    const uint32_t aso1 = (uint32_t)((ar + 64) * 64 + ((acn ^ (((ar + 64) >> 1) & 3)) << 4));
    const uint32_t bso0 = (uint32_t)(8192 + bk * 256 + ((bcn ^ (bk & 7)) << 4));
    const uint32_t bso1 = (uint32_t)(8192 + (bk + 16) * 256 + ((bcn ^ ((bk + 16) & 7)) << 4));

    const int lr = lane & 15, lc = lane >> 4;
    const int arow[2] = { wm * 32 + lr, wm * 32 + 16 + lr };
    const uint32_t aswz[2] = { (uint32_t)((arow[0] >> 1) & 3), (uint32_t)((arow[1] >> 1) & 3) };
    const uint32_t bswzk = (uint32_t)(lr & 7);

    float acc[2][8][4];
    #pragma unroll
    for (int mt = 0; mt < 2; mt++)
        #pragma unroll
        for (int nt = 0; nt < 8; nt++)
            #pragma unroll
            for (int q = 0; q < 4; q++) acc[mt][nt][q] = 0.f;

    const int NS = KTOT >> 5;

    auto issue = [&](int ss) {
        const int kg = ss * 32;
        const uint32_t st = smB + (uint32_t)((ss % 3) * 16384);
        cpa16(st + aso0, Ablk + (size_t)ar * KTOT + kg + acn * 8);
        cpa16(st + aso1, Ablk + (size_t)(ar + 64) * KTOT + kg + acn * 8);
        cpa16(st + bso0, Bblk + (size_t)(kg + bk) * N + bcn * 8);
        cpa16(st + bso1, Bblk + (size_t)(kg + bk + 16) * N + bcn * 8);
        CPA_COMMIT();
    };

    issue(0);
    issue(1);

    #pragma unroll 1
    for (int s = 0; s < NS; s++) {
        if (s + 1 < NS) { CPA_WAIT(1); } else { CPA_WAIT(0); }
        __syncthreads();
        if (s + 2 < NS) issue(s + 2);

        const uint32_t aB = smB + (uint32_t)((s % 3) * 16384);
        const uint32_t bB = aB + 8192;
        #pragma unroll
        for (int ks = 0; ks < 2; ks++) {
            uint32_t af[2][4], bf[4][4];
            #pragma unroll
            for (int mt = 0; mt < 2; mt++) {
                const uint32_t chunk = ((uint32_t)(ks * 2 + lc)) ^ aswz[mt];
                ldm_x4(af[mt], aB + (uint32_t)(arow[mt] * 64) + (chunk << 4));
            }
            const uint32_t kk = (uint32_t)(ks * 16 + lr);
            #pragma unroll
            for (int n16 = 0; n16 < 4; n16++) {
                const uint32_t cn = ((uint32_t)(wn * 8 + n16 * 2 + lc)) ^ bswzk;
                ldm_x4_t(bf[n16], bB + kk * 256 + (cn << 4));
            }
            #pragma unroll
            for (int mt = 0; mt < 2; mt++)
                #pragma unroll
                for (int nt = 0; nt < 8; nt++)
                    mma_f16(acc[mt][nt], af[mt], &bf[nt >> 1][(nt & 1) * 2]);
        }
    }

    const int rbase = brow * 128 + wm * 32 + (lane >> 2);
    const int cbase = bcol * 128 + wn * 64 + (lane & 3) * 2;
    #pragma unroll
    for (int mt = 0; mt < 2; mt++) {
        #pragma unroll
        for (int nt = 0; nt < 8; nt++) {
            const int c = cbase + nt * 8;
            const float2 bv = *(const float2*)(bias + c);
            #pragma unroll
            for (int hrow = 0; hrow < 2; hrow++) {
                const int r = rbase + mt * 16 + hrow * 8;
                float v0 = acc[mt][nt][hrow * 2]     + bv.x;
                float v1 = acc[mt][nt][hrow * 2 + 1] + bv.y;
                if (HALFOUT) {
                    if (RELU) { v0 = fmaxf(v0, 0.f); v1 = fmaxf(v1, 0.f); }
                    *(__half2*)&Ch[(size_t)r * N + c] = __floats2half2_rn(v0, v1);
                } else {
                    const size_t off = (size_t)r * N + c;
                    if (RESID) {
                        const float2 rv = *(const float2*)(res + off);
                        v0 += rv.x; v1 += rv.y;
                    }
                    float2 ov; ov.x = v0; ov.y = v1;
                    *(float2*)(C + off) = ov;
                }
            }
        }
    }
}

// ---------------- HMMA windowed flash attention -> g_ctx (fp16) --------------
// q-tile 128, 8 warps, each warp owns 16 q-rows x full 64-key S stripe.
// smem: Qs 128x64 h (16KB), Ks 64x64 (8KB), Vs 64x64 (8KB), rp 512 f32 (2KB).
__global__ __launch_bounds__(256) void attn_kernel(const float* __restrict__ res_pos)
{
    __shared__ __align__(16) __half Qs[128 * 64];
    __shared__ __align__(16) __half Ks[64 * 64];
    __shared__ __align__(16) __half Vs[64 * 64];
    __shared__ float rp[512];

    const __half* qkv = g_qkvh;
    const int bx = blockIdx.x, h = blockIdx.y, bb = blockIdx.z;
    const int q0 = bx * 128;
    const int tid = threadIdx.x, wid = tid >> 5, lane = tid & 31;
    const int lr = lane & 15, lc = lane >> 4;
    const int r0 = lane >> 2;                     // row-in-16 (and +8)

    const uint32_t qsB = smem_u32(Qs);
    const uint32_t ksB = smem_u32(Ks);
    const uint32_t vsB = smem_u32(Vs);

    for (int i = tid; i < 512; i += 256) rp[i] = res_pos[h * 512 + i];

    // load Q tile (fp16, swizzled rows of 8 chunks)
    #pragma unroll
    for (int i = 0; i < 4; i++) {
        const int idx = i * 256 + tid;
        const int r = idx >> 3, c = idx & 7;
        *(uint4*)((char*)Qs + r * 128 + (((uint32_t)c ^ (r & 7)) << 4)) =
            *(const uint4*)(qkv + (size_t)(bb * 2048 + q0 + r) * 3072 + h * 64 + c * 8);
    }
    __syncthreads();

    // Q fragments (kept in regs across all k-tiles)
    uint32_t qf[4][4];
    #pragma unroll
    for (int ks = 0; ks < 4; ks++) {
        const int row = wid * 16 + lr;
        const uint32_t chunk = ((uint32_t)(2 * ks + lc)) ^ (row & 7);
        ldm_x4(qf[ks], qsB + (uint32_t)(row * 128) + (chunk << 4));
    }

    float m0 = -1e30f, m8 = -1e30f, l0 = 0.f, l8 = 0.f;
    float of[8][4];
    #pragma unroll
    for (int nt = 0; nt < 8; nt++)
        #pragma unroll
        for (int q = 0; q < 4; q++) of[nt][q] = 0.f;

    const int ktlo = (q0 >= 511) ? ((q0 - 511) >> 6) : 0;
    const int kthi = (q0 + 127) >> 6;

    for (int kt = ktlo; kt <= kthi; kt++) {
        __syncthreads();   // prior ldmatrix reads of Ks/Vs done
        #pragma unroll
        for (int i = 0; i < 4; i++) {
            const int idx = i * 256 + tid;
            const int arr = idx >> 9, rem = idx & 511;
            const int r = rem >> 3, c = rem & 7;
            const uint4 v = *(const uint4*)(qkv + (size_t)(bb * 2048 + kt * 64 + r) * 3072
                                            + 1024 + arr * 1024 + h * 64 + c * 8);
            char* dst = arr ? (char*)Vs : (char*)Ks;
            *(uint4*)(dst + r * 128 + (((uint32_t)c ^ (r & 7)) << 4)) = v;
        }
        __syncthreads();

        // S = Q K^T  (warp: 16 rows x 64 keys = 8 n-tiles)
        float sc[8][4];
        #pragma unroll
        for (int nt = 0; nt < 8; nt++)
            #pragma unroll
            for (int q = 0; q < 4; q++) sc[nt][q] = 0.f;
        #pragma unroll
        for (int cd = 0; cd < 4; cd++) {          // hd 16-chunks (k-dim)
            uint32_t kb[4][4];
            #pragma unroll
            for (int g = 0; g < 4; g++) {         // key 16-groups
                const int kr = g * 16 + lr;
                const uint32_t chunk = ((uint32_t)(2 * cd + lc)) ^ (kr & 7);
                ldm_x4(kb[g], ksB + (uint32_t)(kr * 128) + (chunk << 4));
            }
            #pragma unroll
            for (int nt = 0; nt < 8; nt++) {
                uint32_t bp[2];
                const int g = nt >> 1;
                if (nt & 1) { bp[0] = kb[g][1]; bp[1] = kb[g][3]; }
                else        { bp[0] = kb[g][0]; bp[1] = kb[g][2]; }
                mma_f16(sc[nt], qf[cd], bp);
            }
        }

        // bias + window mask
        const int qr = q0 + wid * 16 + r0;
        #pragma unroll
        for (int nt = 0; nt < 8; nt++) {
            const int key0 = kt * 64 + nt * 8 + (lane & 3) * 2;
            #pragma unroll
            for (int j = 0; j < 2; j++) {
                const int dd  = qr - (key0 + j);
                const int dd8 = dd + 8;
                sc[nt][j]     = (dd  >= 0 && dd  < 512) ? sc[nt][j]     * 0.125f + rp[dd]  : -1e30f;
                sc[nt][2 + j] = (dd8 >= 0 && dd8 < 512) ? sc[nt][2 + j] * 0.125f + rp[dd8] : -1e30f;
            }
        }

        // online softmax for rows r0 and r0+8
        float t0 = -1e30f, t8 = -1e30f;
        #pragma unroll
        for (int nt = 0; nt < 8; nt++) {
            t0 = fmaxf(t0, fmaxf(sc[nt][0], sc[nt][1]));
            t8 = fmaxf(t8, fmaxf(sc[nt][2], sc[nt][3]));
        }
        #pragma unroll
        for (int o = 1; o <= 2; o <<= 1) {
            t0 = fmaxf(t0, __shfl_xor_sync(0xffffffffu, t0, o));
            t8 = fmaxf(t8, __shfl_xor_sync(0xffffffffu, t8, o));
        }
        const float mn0 = fmaxf(m0, t0), mn8 = fmaxf(m8, t8);
        const float al0 = __expf(m0 - mn0), al8 = __expf(m8 - mn8);
        m0 = mn0; m8 = mn8;
        float rs0 = 0.f, rs8 = 0.f;
        #pragma unroll
        for (int nt = 0; nt < 8; nt++) {
            sc[nt][0] = __expf(sc[nt][0] - mn0); rs0 += sc[nt][0];
            sc[nt][1] = __expf(sc[nt][1] - mn0); rs0 += sc[nt][1];
            sc[nt][2] = __expf(sc[nt][2] - mn8); rs8 += sc[nt][2];
            sc[nt][3] = __expf(sc[nt][3] - mn8); rs8 += sc[nt][3];
        }
        #pragma unroll
        for (int o = 1; o <= 2; o <<= 1) {
            rs0 += __shfl_xor_sync(0xffffffffu, rs0, o);
            rs8 += __shfl_xor_sync(0xffffffffu, rs8, o);
        }
        l0 = l0 * al0 + rs0;
        l8 = l8 * al8 + rs8;
        #pragma unroll
        for (int nt = 0; nt < 8; nt++) {
            of[nt][0] *= al0; of[nt][1] *= al0;
            of[nt][2] *= al8; of[nt][3] *= al8;
        }

        // O += P V  (P fragments from S accumulators; V via trans ldmatrix)
        #pragma unroll
        for (int ks = 0; ks < 4; ks++) {          // key 16-steps (k-dim)
            uint32_t ap[4];
            __half2 h0 = __floats2half2_rn(sc[2 * ks][0],     sc[2 * ks][1]);
            __half2 h1 = __floats2half2_rn(sc[2 * ks][2],     sc[2 * ks][3]);
            __half2 h2 = __floats2half2_rn(sc[2 * ks + 1][0], sc[2 * ks + 1][1]);
            __half2 h3 = __floats2half2_rn(sc[2 * ks + 1][2], sc[2 * ks + 1][3]);
            ap[0] = *(uint32_t*)&h0; ap[1] = *(uint32_t*)&h1;
            ap[2] = *(uint32_t*)&h2; ap[3] = *(uint32_t*)&h3;
            uint32_t vb[4][4];
            const int kk = ks * 16 + lr;
            #pragma unroll
            for (int nv = 0; nv < 4; nv++) {
                const uint32_t cn = ((uint32_t)(2 * nv + lc)) ^ (kk & 7);
                ldm_x4_t(vb[nv], vsB + (uint32_t)(kk * 128) + (cn << 4));
            }
            #pragma unroll
            for (int nt = 0; nt < 8; nt++)
                mma_f16(of[nt], ap, &vb[nt >> 1][(nt & 1) * 2]);
        }
    }

    // epilogue: O /= l, write fp16 ctx
    const float rl0 = 1.f / l0, rl8 = 1.f / l8;
    const int rowA = bb * 2048 + q0 + wid * 16 + r0;
    #pragma unroll
    for (int nt = 0; nt < 8; nt++) {
        const int c = h * 64 + nt * 8 + (lane & 3) * 2;
        *(__half2*)&g_ctx[(size_t)rowA * 1024 + c] =
            __floats2half2_rn(of[nt][0] * rl0, of[nt][1] * rl0);
        *(__half2*)&g_ctx[(size_t)(rowA + 8) * 1024 + c] =
            __floats2half2_rn(of[nt][2] * rl8, of[nt][3] * rl8);
    }
}

// ---------------- launch: kernel launches ONLY ----------------
extern "C" void kernel_launch(void* const* d_in, const int* in_sizes, int n_in,
                              void* d_out, int out_size)
{
    (void)in_sizes; (void)n_in; (void)out_size;
    const float* x      = (const float*)d_in[0];
    const float* respos = (const float*)d_in[1];
    const float* w_qkv  = (const float*)d_in[2];
    const float* b_qkv  = (const float*)d_in[3];
    const float* w_out  = (const float*)d_in[4];
    const float* b_out  = (const float*)d_in[5];
    const float* w1     = (const float*)d_in[6];
    const float* b1     = (const float*)d_in[7];
    const float* w2     = (const float*)d_in[8];
    const float* b2     = (const float*)d_in[9];
    const float* ln1_g  = (const float*)d_in[10];
    const float* ln1_b  = (const float*)d_in[11];
    const float* ln2_g  = (const float*)d_in[12];
    const float* ln2_b  = (const float*)d_in[13];
    float* out = (float*)d_out;

    cast_w_kernel<<<3072, 256>>>(w_qkv, 3);
    cast_w_kernel<<<1024, 256>>>(w_out, 4);
    cast_w_kernel<<<4096, 256>>>(w1,    5);
    cast_w_kernel<<<4096, 256>>>(w2,    6);

    // 1. ln1 -> g_ln (fp16)
    ln_h_kernel<<<MROWS, 256>>>(x, 0, ln1_g, ln1_b);
    // 2. qkv = ln1 @ wqkv + b_qkv -> g_qkvh (fp16)
    gemm_mma<false, false, true><<<dim3(24, 32), 256>>>(
        3072, 1024, 1, 3, b_qkv, nullptr, 0, nullptr, 8);
    // 3. HMMA attention -> g_ctx (fp16)
    attn_kernel<<<dim3(16, 16, 2), 256>>>(respos);
    // 4. x1 = x + ctx @ wout + b_out -> g_x1 (fp32)
    gemm_mma<false, true, false><<<dim3(8, 32), 256>>>(
        1024, 1024, 2, 4, b_out, x, 0, nullptr, 2);
    // 5. ln2 -> g_ln
    ln_h_kernel<<<MROWS, 256>>>(nullptr, 2, ln2_g, ln2_b);
    // 6. ffn1 = relu(ln2 @ w1 + b1) -> g_ffn1 (fp16)
    gemm_mma<true, false, true><<<dim3(32, 32), 256>>>(
        4096, 1024, 1, 5, b1, nullptr, 0, nullptr, 7);
    // 7. out = x1 + ffn1 @ w2 + b2 -> d_out (fp32)
    gemm_mma<false, true, false><<<dim3(8, 32), 256>>>(
        1024, 4096, 7, 6, b2, nullptr, 2, out, 0);
}